// round 4
// baseline (speedup 1.0000x reference)
#include <cuda_runtime.h>
#include <math.h>

#define B_ 2
#define C_ 256
#define N_ 4096
#define D_ 64
#define K_ 32
#define M_ 256
#define R_ 416
#define RPAD 448
#define INVSCALE (1.0f/8.000001f)

// ----------------------------- scratch -----------------------------
__device__ float g_W[R_*C_];
__device__ float g_Wt[C_*RPAD];        // transposed + padded weights for GEMM
__device__ float g_bias[R_];
__device__ float g_P[B_*R_*N_];        // [sem(32); q(64); k(64); fv(256)] x N
__device__ float g_sem[B_*K_*N_];
__device__ int   g_ti[B_*K_*M_];
__device__ int   g_cnt[B_*K_];
__device__ int   g_plist[B_*K_*N_];
__device__ float g_qT[B_*N_*D_];
__device__ float g_kT[B_*N_*D_];
__device__ float g_fvT[B_*N_*C_];
__device__ float g_xT[B_*N_*C_];
__device__ float g_part[8*B_*K_*320];
__device__ float g_RK[B_*K_*D_];
__device__ float g_RFV[B_*K_*C_];
__device__ float g_outT[B_*N_*C_];

// ----------------------------- kernels -----------------------------
// zero region counters + zero the pad rows of g_Wt (r in [416,448))
__global__ void k_zero() {
    int g = blockIdx.x*256 + threadIdx.x;     // 32*256 = 8192
    if (g < B_*K_) g_cnt[g] = 0;
    int c = g >> 5, r = R_ + (g & 31);
    g_Wt[c*RPAD + r] = 0.f;
}

// Build Wcat = [sem_w; q_w; k_w; fuse_w@v_w], bias, and transposed copy
__global__ void k_prep(const float* __restrict__ sem_w, const float* __restrict__ sem_b,
                       const float* __restrict__ q_w,  const float* __restrict__ k_w,
                       const float* __restrict__ v_w,  const float* __restrict__ fuse_w) {
    __shared__ float fw[C_];
    int r = blockIdx.x, c = threadIdx.x;
    if (r >= 160) fw[c] = fuse_w[(r-160)*C_ + c];
    __syncthreads();
    float val;
    if (r < 32)       val = sem_w[r*C_ + c];
    else if (r < 96)  val = q_w[(r-32)*C_ + c];
    else if (r < 160) val = k_w[(r-96)*C_ + c];
    else {
        float acc = 0.f;
        #pragma unroll 8
        for (int m = 0; m < C_; m++) acc += fw[m] * v_w[m*C_ + c];
        val = acc;
    }
    g_W[r*C_ + c] = val;
    g_Wt[c*RPAD + r] = val;
    if (c == 0) g_bias[r] = (r < 32) ? sem_b[r] : 0.f;
}

// P[b,r,n] = Wcat[r,:] @ x[b,:,n] + bias[r]
// 64r x 128n tile, BK=16, 256 threads, 4x8 micro, double-buffered SMEM.
__global__ void __launch_bounds__(256) k_gemm(const float* __restrict__ x) {
    __shared__ float As[2][16][64];
    __shared__ float Bs[2][16][128];
    int n0 = blockIdx.x*128, r0 = blockIdx.y*64, b = blockIdx.z;
    int tid = threadIdx.x;
    int ty = tid >> 4, tx = tid & 15;          // r = r0+ty*4+i, n = n0+tx*8+j
    const float* xb = x + b*C_*N_;

    int la_k = tid >> 4;                        // 0..15
    int la_r = (tid & 15) * 4;                  // 0..60
    int lb_k = tid >> 5;                        // 0..7 (and +8)
    int lb_n = (tid & 31) * 4;                  // 0..124

    float4 a_pre  = *(const float4*)&g_Wt[la_k*RPAD + r0 + la_r];
    float4 b_pre0 = *(const float4*)&xb[lb_k*N_ + n0 + lb_n];
    float4 b_pre1 = *(const float4*)&xb[(lb_k+8)*N_ + n0 + lb_n];

    float acc[4][8] = {};
    int buf = 0;
    for (int kc = 0; kc < C_; kc += 16) {
        *(float4*)&As[buf][la_k][la_r] = a_pre;
        *(float4*)&Bs[buf][lb_k][lb_n] = b_pre0;
        *(float4*)&Bs[buf][lb_k+8][lb_n] = b_pre1;
        __syncthreads();
        if (kc + 16 < C_) {
            a_pre  = *(const float4*)&g_Wt[(kc+16+la_k)*RPAD + r0 + la_r];
            b_pre0 = *(const float4*)&xb[(kc+16+lb_k)*N_ + n0 + lb_n];
            b_pre1 = *(const float4*)&xb[(kc+16+lb_k+8)*N_ + n0 + lb_n];
        }
        #pragma unroll
        for (int kk = 0; kk < 16; kk++) {
            float4 av  = *(const float4*)&As[buf][kk][ty*4];
            float4 bv0 = *(const float4*)&Bs[buf][kk][tx*8];
            float4 bv1 = *(const float4*)&Bs[buf][kk][tx*8+4];
            float aa[4] = {av.x, av.y, av.z, av.w};
            float bb[8] = {bv0.x, bv0.y, bv0.z, bv0.w, bv1.x, bv1.y, bv1.z, bv1.w};
            #pragma unroll
            for (int i = 0; i < 4; i++)
                #pragma unroll
                for (int j = 0; j < 8; j++) acc[i][j] += aa[i]*bb[j];
        }
        buf ^= 1;
    }
    #pragma unroll
    for (int i = 0; i < 4; i++) {
        int r = r0 + ty*4 + i;
        if (r < R_) {
            float bi = g_bias[r];
            float4 o0 = make_float4(acc[i][0]+bi, acc[i][1]+bi, acc[i][2]+bi, acc[i][3]+bi);
            float4 o1 = make_float4(acc[i][4]+bi, acc[i][5]+bi, acc[i][6]+bi, acc[i][7]+bi);
            *(float4*)&g_P[(b*R_ + r)*N_ + n0 + tx*8]     = o0;
            *(float4*)&g_P[(b*R_ + r)*N_ + n0 + tx*8 + 4] = o1;
        }
    }
}

// softmax over K per position + argmax bucketing
__global__ void k_sem() {
    int gid = blockIdx.x*256 + threadIdx.x;       // 8192 total
    int b = gid >> 12, n = gid & (N_-1);
    float l[K_];
    float mx = -INFINITY; int am = 0;
    #pragma unroll
    for (int k = 0; k < K_; k++) {
        l[k] = g_P[(b*R_ + k)*N_ + n];
        if (l[k] > mx) { mx = l[k]; am = k; }
    }
    float s = 0.f;
    #pragma unroll
    for (int k = 0; k < K_; k++) { l[k] = expf(l[k]-mx); s += l[k]; }
    float inv = 1.f/s;
    #pragma unroll
    for (int k = 0; k < K_; k++) g_sem[(b*K_ + k)*N_ + n] = l[k]*inv;
    int slot = atomicAdd(&g_cnt[b*K_ + am], 1);
    g_plist[(b*K_+am)*N_ + slot] = n;
}

// exact top-256 per (b,k): bitonic sort of 4096 packed keys
__global__ void __launch_bounds__(1024) k_sort() {
    __shared__ unsigned long long s[N_];
    int bk = blockIdx.x; int b = bk >> 5, k = bk & 31;
    int tid = threadIdx.x;
    for (int i = tid; i < N_; i += 1024) {
        float v = g_sem[(b*K_+k)*N_ + i];
        unsigned long long key = ((unsigned long long)__float_as_uint(v) << 32)
                               | (unsigned)(0xFFFFFFFFu - (unsigned)i);
        s[i] = ~key;   // ascending sort of ~key == descending of key
    }
    __syncthreads();
    for (int sz = 2; sz <= N_; sz <<= 1) {
        for (int str = sz >> 1; str > 0; str >>= 1) {
            for (int i = tid; i < N_; i += 1024) {
                int l = i ^ str;
                if (l > i) {
                    unsigned long long a = s[i], c = s[l];
                    bool up = ((i & sz) == 0);
                    if ((a > c) == up) { s[i] = c; s[l] = a; }
                }
            }
            __syncthreads();
        }
    }
    if (tid < M_) {
        unsigned long long key = ~s[tid];
        g_ti[(b*K_+k)*M_ + tid] = (int)(0xFFFFFFFFu - (unsigned)(key & 0xFFFFFFFFu));
    }
}

// generic tiled transposes (mode selects src/dst)
__global__ void k_transp(int mode, const float* __restrict__ xin, float* __restrict__ dout) {
    const float* src; float* dst; int Rr, Nn, rowOff, sBS;
    if      (mode == 0) { src = g_P;    dst = g_qT;  Rr = 64;  Nn = N_;  rowOff = 32;  sBS = R_*N_; }
    else if (mode == 1) { src = g_P;    dst = g_kT;  Rr = 64;  Nn = N_;  rowOff = 96;  sBS = R_*N_; }
    else if (mode == 2) { src = g_P;    dst = g_fvT; Rr = 256; Nn = N_;  rowOff = 160; sBS = R_*N_; }
    else if (mode == 3) { src = xin;    dst = g_xT;  Rr = 256; Nn = N_;  rowOff = 0;   sBS = C_*N_; }
    else                { src = g_outT; dst = dout;  Rr = N_;  Nn = 256; rowOff = 0;   sBS = N_*C_; }
    __shared__ float t[32][33];
    int b = blockIdx.z;
    int x0 = blockIdx.x*32, r0 = blockIdx.y*32;
    int tx = threadIdx.x, ty = threadIdx.y;
    #pragma unroll
    for (int i = 0; i < 32; i += 8)
        t[ty+i][tx] = src[b*sBS + (rowOff + r0 + ty + i)*Nn + x0 + tx];
    __syncthreads();
    #pragma unroll
    for (int i = 0; i < 32; i += 8)
        dst[b*Nn*Rr + (x0 + ty + i)*Rr + r0 + tx] = t[tx][ty+i];
}

// region_k / region_fv = sem @ [k; fv]^T, split over N into 8 partials
__global__ void __launch_bounds__(256) k_region() {
    __shared__ float ss[32*65];
    __shared__ float ps[64*65];
    int ct = blockIdx.x, sp = blockIdx.y, b = blockIdx.z;
    int tid = threadIdx.x;
    int kk = tid & 31, cg = tid >> 5;   // c0 = cg*8
    float acc[8] = {};
    for (int nch = 0; nch < 8; nch++) {
        int nn0 = sp*512 + nch*64;
        #pragma unroll
        for (int i = 0; i < 8; i++) {
            int e = tid + i*256; int kr = e >> 6, nn = e & 63;
            ss[kr*65+nn] = g_sem[(b*K_+kr)*N_ + nn0 + nn];
        }
        #pragma unroll
        for (int i = 0; i < 16; i++) {
            int e = tid + i*256; int c = e >> 6, nn = e & 63;
            ps[c*65+nn] = g_P[(b*R_ + 96 + ct*64 + c)*N_ + nn0 + nn];
        }
        __syncthreads();
        for (int nn = 0; nn < 64; nn++) {
            float sv = ss[kk*65+nn];
            #pragma unroll
            for (int j = 0; j < 8; j++) acc[j] += sv * ps[(cg*8+j)*65+nn];
        }
        __syncthreads();
    }
    #pragma unroll
    for (int j = 0; j < 8; j++) {
        int o = ct*64 + cg*8 + j;
        g_part[((sp*B_+b)*K_+kk)*320 + o] = acc[j];
    }
}

__global__ void k_reduce() {
    int og = blockIdx.x*256 + threadIdx.x;           // 20480 total
    int b = og / (K_*320); int rem = og % (K_*320);
    int kk = rem / 320, o = rem % 320;
    float s = 0.f;
    #pragma unroll
    for (int sp = 0; sp < 8; sp++) s += g_part[((sp*B_+b)*K_+kk)*320 + o];
    if (o < 64) g_RK[(b*K_+kk)*D_ + o] = s;
    else        g_RFV[(b*K_+kk)*C_ + (o-64)] = s;
}

// fused main: sims -> top8 -> sparse, dense attn, combine, residual, channel-LN
// Each warp processes 4 positions per pool pass (4x SMEM reuse on sims).
__global__ void __launch_bounds__(256) k_main(const float* __restrict__ alpha_p,
                                              const float* __restrict__ fuse_b,
                                              const float* __restrict__ ln_g,
                                              const float* __restrict__ ln_b) {
    extern __shared__ float sm[];
    float* s_pkT = sm;                         // 64*257
    float* s_rfv = s_pkT + 64*257;             // 32*256
    float* s_rk  = s_rfv + 32*256;             // 32*65
    float* s_q   = s_rk  + 32*65;              // 8 warps * 4 pos * 64
    int*   s_pool= (int*)(s_q + 8*256);        // 256

    int chunk = blockIdx.x, reg = blockIdx.y, b = blockIdx.z;
    int cnt = g_cnt[b*K_ + reg];
    int base = chunk*64;
    if (base >= cnt) return;
    int tid = threadIdx.x, lane = tid & 31, w = tid >> 5;

    if (tid < M_) s_pool[tid] = g_ti[(b*K_+reg)*M_ + tid];
    __syncthreads();
    #pragma unroll 4
    for (int i = 0; i < 64; i++) {
        int e = tid + i*256;
        int m = e >> 6, d = e & 63;
        s_pkT[d*257 + m] = g_kT[(b*N_ + s_pool[m])*D_ + d];
    }
    #pragma unroll
    for (int i = 0; i < 32; i++) s_rfv[tid + i*256] = g_RFV[b*K_*C_ + tid + i*256];
    #pragma unroll
    for (int i = 0; i < 8; i++) {
        int e = tid + i*256; int kk = e >> 6, d = e & 63;
        s_rk[kk*65+d] = g_RK[(b*K_+kk)*D_ + d];
    }
    __syncthreads();

    float a = 1.f/(1.f + expf(-alpha_p[0]));
    int pend = min(base+64, cnt);
    float* qw = s_q + w*256;

    for (int g = 0; g < 2; g++) {
        int p0 = base + w*8 + g*4;
        if (p0 >= pend) break;
        int nv = min(4, pend - p0);
        int n[4] = {0, 0, 0, 0};
        #pragma unroll
        for (int i = 0; i < 4; i++) {
            if (i < nv) {
                n[i] = g_plist[(b*K_+reg)*N_ + p0 + i];
                qw[i*64 + lane]      = g_qT[(b*N_+n[i])*D_ + lane];
                qw[i*64 + 32 + lane] = g_qT[(b*N_+n[i])*D_ + 32 + lane];
            }
        }
        __syncwarp();

        // sims[i][mi] over the 256-entry pool; lane owns m = mi*32+lane
        float sims[4][8] = {};
        for (int d = 0; d < 64; d++) {
            const float* row = s_pkT + d*257;
            float r8[8];
            #pragma unroll
            for (int mi = 0; mi < 8; mi++) r8[mi] = row[mi*32 + lane];
            #pragma unroll
            for (int i = 0; i < 4; i++) {
                float qd = qw[i*64 + d];
                #pragma unroll
                for (int mi = 0; mi < 8; mi++) sims[i][mi] += qd * r8[mi];
            }
        }

        for (int i = 0; i < nv; i++) {
            float sv[8];
            #pragma unroll
            for (int mi = 0; mi < 8; mi++) sv[mi] = sims[i][mi] * INVSCALE;

            // exact warp top-8 (value desc, pool index asc on ties)
            float tv[8]; int tm[8];
            unsigned used = 0;
            #pragma unroll
            for (int t = 0; t < 8; t++) {
                float bv = -INFINITY; int bm = 1 << 30;
                #pragma unroll
                for (int mi = 0; mi < 8; mi++) {
                    if (!(used & (1u << mi))) {
                        float v = sv[mi]; int m = mi*32 + lane;
                        if (v > bv || (v == bv && m < bm)) { bv = v; bm = m; }
                    }
                }
                #pragma unroll
                for (int off = 16; off > 0; off >>= 1) {
                    float ov = __shfl_xor_sync(0xFFFFFFFFu, bv, off);
                    int   om = __shfl_xor_sync(0xFFFFFFFFu, bm, off);
                    if (ov > bv || (ov == bv && om < bm)) { bv = ov; bm = om; }
                }
                tv[t] = bv; tm[t] = bm;
                if ((bm & 31) == lane) used |= 1u << (bm >> 5);
            }
            // softmax over tv (tv[0] is the max)
            float ww[8], wsum = 0.f;
            #pragma unroll
            for (int t = 0; t < 8; t++) { ww[t] = expf(tv[t] - tv[0]); wsum += ww[t]; }
            float winv = 1.f/wsum;
            // sparse branch: gather fv rows
            float fs[8] = {};
            #pragma unroll
            for (int t = 0; t < 8; t++) {
                float att = ww[t]*winv;
                int gidx = s_pool[tm[t]];
                const float* fvrow = g_fvT + (b*N_ + gidx)*C_;
                #pragma unroll
                for (int j = 0; j < 8; j++) fs[j] += att * fvrow[j*32 + lane];
            }
            // dense branch: logit for region k = lane
            float lg = 0.f;
            for (int d = 0; d < 64; d++) lg += qw[i*64 + d]*s_rk[lane*65 + d];
            lg *= INVSCALE;
            float mx = lg;
            #pragma unroll
            for (int off = 16; off > 0; off >>= 1)
                mx = fmaxf(mx, __shfl_xor_sync(0xFFFFFFFFu, mx, off));
            float ev = expf(lg - mx), es = ev;
            #pragma unroll
            for (int off = 16; off > 0; off >>= 1) es += __shfl_xor_sync(0xFFFFFFFFu, es, off);
            float attn = ev/es;
            float fc[8] = {};
            for (int kk = 0; kk < K_; kk++) {
                float ak = __shfl_sync(0xFFFFFFFFu, attn, kk);
                const float* rrow = s_rfv + kk*256;
                #pragma unroll
                for (int j = 0; j < 8; j++) fc[j] += ak * rrow[j*32 + lane];
            }
            // combine + fuse bias + residual + channel LayerNorm
            float pre[8], sum = 0.f, sq = 0.f;
            const float* xrow = g_xT + (b*N_+n[i])*C_;
            #pragma unroll
            for (int j = 0; j < 8; j++) {
                int c = j*32 + lane;
                float f = a*fc[j] + (1.f - a)*fs[j] + fuse_b[c];
                float v = xrow[c] + f;
                pre[j] = v; sum += v; sq += v*v;
            }
            #pragma unroll
            for (int off = 16; off > 0; off >>= 1) {
                sum += __shfl_xor_sync(0xFFFFFFFFu, sum, off);
                sq  += __shfl_xor_sync(0xFFFFFFFFu, sq,  off);
            }
            float mu = sum * (1.f/256.f);
            float var = sq * (1.f/256.f) - mu*mu;
            float rstd = rsqrtf(var + 1e-5f);
            float* orow = g_outT + (b*N_+n[i])*C_;
            #pragma unroll
            for (int j = 0; j < 8; j++) {
                int c = j*32 + lane;
                orow[c] = (pre[j]-mu)*rstd*ln_g[c] + ln_b[c];
            }
        }
    }
}

// ----------------------------- launch -----------------------------
extern "C" void kernel_launch(void* const* d_in, const int* in_sizes, int n_in,
                              void* d_out, int out_size) {
    const float* x      = (const float*)d_in[0];
    const float* sem_w  = (const float*)d_in[1];
    const float* sem_b  = (const float*)d_in[2];
    const float* q_w    = (const float*)d_in[3];
    const float* k_w    = (const float*)d_in[4];
    const float* v_w    = (const float*)d_in[5];
    const float* fuse_w = (const float*)d_in[6];
    const float* fuse_b = (const float*)d_in[7];
    const float* alpha  = (const float*)d_in[8];
    const float* ln_g   = (const float*)d_in[9];
    const float* ln_b   = (const float*)d_in[10];
    float* out = (float*)d_out;

    const int SMEM_MAIN = (64*257 + 32*256 + 32*65 + 8*256)*4 + 256*4;
    cudaFuncSetAttribute((const void*)k_main,
                         cudaFuncAttributeMaxDynamicSharedMemorySize, SMEM_MAIN);

    k_zero<<<32, 256>>>();
    k_prep<<<R_, 256>>>(sem_w, sem_b, q_w, k_w, v_w, fuse_w);
    k_gemm<<<dim3(32, 7, B_), 256>>>(x);
    k_sem<<<32, 256>>>();
    k_sort<<<B_*K_, 1024>>>();
    k_transp<<<dim3(128, 2, B_), dim3(32, 8)>>>(0, x, out);  // qT
    k_transp<<<dim3(128, 2, B_), dim3(32, 8)>>>(1, x, out);  // kT
    k_transp<<<dim3(128, 8, B_), dim3(32, 8)>>>(2, x, out);  // fvT
    k_transp<<<dim3(128, 8, B_), dim3(32, 8)>>>(3, x, out);  // xT
    k_region<<<dim3(5, 8, B_), 256>>>();
    k_reduce<<<80, 256>>>();
    k_main<<<dim3(64, K_, B_), 256, SMEM_MAIN>>>(alpha, fuse_b, ln_g, ln_b);
    k_transp<<<dim3(8, 128, B_), dim3(32, 8)>>>(4, x, out);  // outT -> (B,C,N)
}

// round 5
// speedup vs baseline: 1.2170x; 1.2170x over previous
#include <cuda_runtime.h>
#include <math.h>

#define B_ 2
#define C_ 256
#define N_ 4096
#define D_ 64
#define K_ 32
#define M_ 256
#define R_ 416
#define RPAD 448
#define INVSCALE (1.0f/8.000001f)
typedef unsigned long long ull;

// ----------------------------- scratch -----------------------------
__device__ float g_Wt[C_*RPAD];        // transposed + padded weights for GEMM
__device__ float g_bias[R_];
__device__ float g_P[B_*R_*N_];        // [sem(32); q(64); k(64); fv(256)] x N
__device__ float g_sem[B_*K_*N_];
__device__ int   g_ti[B_*K_*M_];
__device__ int   g_cnt[B_*K_];
__device__ int   g_plist[B_*K_*N_];
__device__ float g_qT[B_*N_*D_];
__device__ float g_kT[B_*N_*D_];
__device__ float g_fvT[B_*N_*C_];
__device__ float g_xT[B_*N_*C_];
__device__ float g_part[8*B_*K_*320];
__device__ float g_RK[B_*K_*D_];
__device__ float g_RFV[B_*K_*C_];
__device__ float g_outT[B_*N_*C_];

// ----------------------------- k_prep -----------------------------
// blocks 0..9: copy sem/q/k rows; blocks 10..25: compute fv = fuse_w @ v_w rows.
// block 0 additionally zeroes counters and g_Wt pad rows.
__global__ void __launch_bounds__(256) k_prep(
    const float* __restrict__ sem_w, const float* __restrict__ sem_b,
    const float* __restrict__ q_w,  const float* __restrict__ k_w,
    const float* __restrict__ v_w,  const float* __restrict__ fuse_w) {
    int blk = blockIdx.x, tid = threadIdx.x;
    if (blk < 10) {
        #pragma unroll
        for (int it = 0; it < 16; it++) {
            int e = tid + it*256;
            int r = blk*16 + (e >> 8), c = e & 255;
            float val = (r < 32) ? sem_w[r*C_ + c]
                      : (r < 96) ? q_w[(r-32)*C_ + c]
                                 : k_w[(r-96)*C_ + c];
            g_Wt[c*RPAD + r] = val;
            if (c == 0) g_bias[r] = (r < 32) ? sem_b[r] : 0.f;
        }
        if (blk == 0) {
            if (tid < B_*K_) g_cnt[tid] = 0;
            for (int i = tid; i < 32*256; i += 256) {
                int rr = R_ + (i & 31), cc = i >> 5;
                g_Wt[cc*RPAD + rr] = 0.f;
            }
        }
    } else {
        int r0 = 160 + (blk-10)*16;
        __shared__ float fw[16*256];
        #pragma unroll
        for (int it = 0; it < 16; it++) {
            int e = tid + it*256;
            fw[e] = fuse_w[(r0-160)*C_ + e];
        }
        __syncthreads();
        float acc[16] = {};
        for (int m = 0; m < C_; m++) {
            float v = v_w[m*C_ + tid];
            #pragma unroll
            for (int rr = 0; rr < 16; rr++) acc[rr] += fw[rr*256 + m] * v;
        }
        #pragma unroll
        for (int rr = 0; rr < 16; rr++) {
            int r = r0 + rr;
            g_Wt[tid*RPAD + r] = acc[rr];
            if (tid == 0) g_bias[r] = 0.f;
        }
    }
}

// ----------------------------- k_gemm -----------------------------
// P[b,r,n] = Wcat[r,:] @ x[b,:,n] + bias[r]
// 64r x 128n tile, BK=16, 256 threads, 4x(4+4) micro (conflict-free), double buffer.
__global__ void __launch_bounds__(256) k_gemm(const float* __restrict__ x) {
    __shared__ float As[2][16][64];
    __shared__ float Bs[2][16][128];
    int n0 = blockIdx.x*128, r0 = blockIdx.y*64, b = blockIdx.z;
    int tid = threadIdx.x;
    int ty = tid >> 4, tx = tid & 15;
    const float* xb = x + b*C_*N_;

    int la_k = tid >> 4;                        // 0..15
    int la_r = (tid & 15) * 4;                  // 0..60
    int lb_k = tid >> 5;                        // 0..7 (and +8)
    int lb_n = (tid & 31) * 4;                  // 0..124

    float4 a_pre  = *(const float4*)&g_Wt[la_k*RPAD + r0 + la_r];
    float4 b_pre0 = *(const float4*)&xb[lb_k*N_ + n0 + lb_n];
    float4 b_pre1 = *(const float4*)&xb[(lb_k+8)*N_ + n0 + lb_n];

    float acc[4][8] = {};
    int buf = 0;
    for (int kc = 0; kc < C_; kc += 16) {
        *(float4*)&As[buf][la_k][la_r]   = a_pre;
        *(float4*)&Bs[buf][lb_k][lb_n]   = b_pre0;
        *(float4*)&Bs[buf][lb_k+8][lb_n] = b_pre1;
        __syncthreads();
        if (kc + 16 < C_) {
            a_pre  = *(const float4*)&g_Wt[(kc+16+la_k)*RPAD + r0 + la_r];
            b_pre0 = *(const float4*)&xb[(kc+16+lb_k)*N_ + n0 + lb_n];
            b_pre1 = *(const float4*)&xb[(kc+16+lb_k+8)*N_ + n0 + lb_n];
        }
        #pragma unroll
        for (int kk = 0; kk < 16; kk++) {
            float4 av  = *(const float4*)&As[buf][kk][ty*4];
            float4 bv0 = *(const float4*)&Bs[buf][kk][tx*4];        // n = tx*4+j
            float4 bv1 = *(const float4*)&Bs[buf][kk][64 + tx*4];   // n = 64+tx*4+j
            float aa[4] = {av.x, av.y, av.z, av.w};
            float bb[8] = {bv0.x, bv0.y, bv0.z, bv0.w, bv1.x, bv1.y, bv1.z, bv1.w};
            #pragma unroll
            for (int i = 0; i < 4; i++)
                #pragma unroll
                for (int j = 0; j < 8; j++) acc[i][j] += aa[i]*bb[j];
        }
        buf ^= 1;
    }
    #pragma unroll
    for (int i = 0; i < 4; i++) {
        int r = r0 + ty*4 + i;
        if (r < R_) {
            float bi = g_bias[r];
            float4 o0 = make_float4(acc[i][0]+bi, acc[i][1]+bi, acc[i][2]+bi, acc[i][3]+bi);
            float4 o1 = make_float4(acc[i][4]+bi, acc[i][5]+bi, acc[i][6]+bi, acc[i][7]+bi);
            *(float4*)&g_P[(b*R_ + r)*N_ + n0 + tx*4]      = o0;
            *(float4*)&g_P[(b*R_ + r)*N_ + n0 + 64 + tx*4] = o1;
        }
    }
}

// ----------------------------- k_sem -----------------------------
__global__ void k_sem() {
    int gid = blockIdx.x*64 + threadIdx.x;        // 8192 total
    int b = gid >> 12, n = gid & (N_-1);
    float l[K_];
    float mx = -INFINITY; int am = 0;
    #pragma unroll
    for (int k = 0; k < K_; k++) {
        l[k] = g_P[(b*R_ + k)*N_ + n];
        if (l[k] > mx) { mx = l[k]; am = k; }
    }
    float s = 0.f;
    #pragma unroll
    for (int k = 0; k < K_; k++) { l[k] = expf(l[k]-mx); s += l[k]; }
    float inv = 1.f/s;
    #pragma unroll
    for (int k = 0; k < K_; k++) g_sem[(b*K_ + k)*N_ + n] = l[k]*inv;
    int slot = atomicAdd(&g_cnt[b*K_ + am], 1);
    g_plist[(b*K_+am)*N_ + slot] = n;
}

// ----------------------------- k_sel -----------------------------
// exact top-256 per (b,k) via histogram select on float bits + boundary sort.
// key = (valbits<<32) | (0xFFFFFFFF - idx); stored as ~key, ascending sort = top first.
__global__ void __launch_bounds__(256) k_sel() {
    __shared__ ull cand[4096];                     // 32 KB (first 16 KB aliased as hist)
    __shared__ ull win[256];
    __shared__ int csum[256];
    __shared__ int s_t, s_A, s_nw, s_nc;
    unsigned* hist = (unsigned*)cand;

    int bk = blockIdx.x; int b = bk >> 5, k = bk & 31;
    int tid = threadIdx.x;
    const float* row = g_sem + (b*K_ + k)*N_;

    for (int i = tid; i < 4096; i += 256) hist[i] = 0;
    __syncthreads();

    unsigned vb[16];
    #pragma unroll
    for (int j = 0; j < 16; j++) {
        vb[j] = __float_as_uint(row[tid + j*256]);
        atomicAdd(&hist[vb[j] >> 20], 1);
    }
    __syncthreads();

    int cs = 0;
    #pragma unroll
    for (int h = 0; h < 16; h++) cs += hist[tid*16 + h];
    csum[tid] = cs;
    __syncthreads();

    if (tid == 0) {
        int acc = 0, tc = 255;
        for (int c = 255; c >= 0; c--) {
            if (acc + csum[c] >= M_) { tc = c; break; }
            acc += csum[c];
        }
        int t = tc*16;
        for (int h = tc*16 + 15; h >= tc*16; h--) {
            int cc = hist[h];
            if (acc + cc >= M_) { t = h; break; }
            acc += cc;
        }
        s_t = t; s_A = acc; s_nw = 0; s_nc = 0;
    }
    __syncthreads();
    int t = s_t, A = s_A, s = M_ - A;
    __syncthreads();   // hist reads done; cand may be overwritten now

    #pragma unroll
    for (int j = 0; j < 16; j++) {
        unsigned v = vb[j];
        int idx = tid + j*256;
        unsigned bkt = v >> 20;
        ull key = ((ull)v << 32) | (unsigned)(0xFFFFFFFFu - (unsigned)idx);
        if ((int)bkt > t) { int p = atomicAdd(&s_nw, 1); win[p] = ~key; }
        else if ((int)bkt == t) { int p = atomicAdd(&s_nc, 1); cand[p] = ~key; }
    }
    __syncthreads();

    int nc = s_nc;
    int P = 1; while (P < nc) P <<= 1;
    for (int i = tid; i < P; i += 256) if (i >= nc) cand[i] = 0xFFFFFFFFFFFFFFFFULL;
    __syncthreads();
    for (int sz = 2; sz <= P; sz <<= 1) {
        for (int str = sz >> 1; str > 0; str >>= 1) {
            for (int i = tid; i < P; i += 256) {
                int l = i ^ str;
                if (l > i) {
                    ull a = cand[i], c2 = cand[l];
                    bool up = ((i & sz) == 0);
                    if ((a > c2) == up) { cand[i] = c2; cand[l] = a; }
                }
            }
            __syncthreads();
        }
    }
    for (int i = tid; i < s; i += 256) win[A + i] = cand[i];
    __syncthreads();
    // final sort of 256 winners
    for (int sz = 2; sz <= 256; sz <<= 1) {
        for (int str = sz >> 1; str > 0; str >>= 1) {
            int i = tid, l = i ^ str;
            if (l > i) {
                ull a = win[i], c2 = win[l];
                bool up = ((i & sz) == 0);
                if ((a > c2) == up) { win[i] = c2; win[l] = a; }
            }
            __syncthreads();
        }
    }
    // win[m] = ~key; low 32 bits of ~key == idx
    g_ti[(b*K_ + k)*M_ + tid] = (int)(unsigned)(win[tid] & 0xFFFFFFFFu);
}

// ----------------------------- transposes -----------------------------
// all input-side transposes in one kernel; y selects target
__global__ void k_transpA(const float* __restrict__ x) {
    __shared__ float t[32][33];
    int b = blockIdx.z, x0 = blockIdx.x*32, y = blockIdx.y;
    const float* src; float* dst; int r0, Rr;
    if      (y < 2)  { src = g_P + (b*R_ + 32)*N_;  dst = g_qT  + b*N_*D_; r0 = y*32;       Rr = D_; }
    else if (y < 4)  { src = g_P + (b*R_ + 96)*N_;  dst = g_kT  + b*N_*D_; r0 = (y-2)*32;   Rr = D_; }
    else if (y < 12) { src = g_P + (b*R_ + 160)*N_; dst = g_fvT + b*N_*C_; r0 = (y-4)*32;   Rr = C_; }
    else             { src = x + b*C_*N_;           dst = g_xT  + b*N_*C_; r0 = (y-12)*32;  Rr = C_; }
    int tx = threadIdx.x, ty = threadIdx.y;
    #pragma unroll
    for (int i = 0; i < 32; i += 8)
        t[ty+i][tx] = src[(r0 + ty + i)*N_ + x0 + tx];
    __syncthreads();
    #pragma unroll
    for (int i = 0; i < 32; i += 8)
        dst[(x0 + ty + i)*Rr + r0 + tx] = t[tx][ty+i];
}

// output transpose: (B,N,C) -> (B,C,N)
__global__ void k_transpO(float* __restrict__ out) {
    __shared__ float t[32][33];
    int b = blockIdx.z, c0 = blockIdx.x*32, n0 = blockIdx.y*32;
    int tx = threadIdx.x, ty = threadIdx.y;
    #pragma unroll
    for (int i = 0; i < 32; i += 8)
        t[ty+i][tx] = g_outT[b*N_*C_ + (n0 + ty + i)*C_ + c0 + tx];
    __syncthreads();
    #pragma unroll
    for (int i = 0; i < 32; i += 8)
        out[b*C_*N_ + (c0 + ty + i)*N_ + n0 + tx] = t[tx][ty+i];
}

// ----------------------------- k_region -----------------------------
// region_k / region_fv = sem @ [k; fv]^T, split over N into 8 partials (float4 inner)
__global__ void __launch_bounds__(256) k_region() {
    __shared__ float ss[32*68];
    __shared__ float ps[64*68];
    int ct = blockIdx.x, sp = blockIdx.y, b = blockIdx.z;
    int tid = threadIdx.x;
    int kk = tid & 31, cg = tid >> 5;
    float acc[8] = {};
    for (int nch = 0; nch < 8; nch++) {
        int nn0 = sp*512 + nch*64;
        #pragma unroll
        for (int i = 0; i < 8; i++) {
            int e = tid + i*256; int kr = e >> 6, nn = e & 63;
            ss[kr*68+nn] = g_sem[(b*K_+kr)*N_ + nn0 + nn];
        }
        #pragma unroll
        for (int i = 0; i < 16; i++) {
            int e = tid + i*256; int c = e >> 6, nn = e & 63;
            ps[c*68+nn] = g_P[(b*R_ + 96 + ct*64 + c)*N_ + nn0 + nn];
        }
        __syncthreads();
        #pragma unroll 4
        for (int nn = 0; nn < 64; nn += 4) {
            float4 sv = *(const float4*)&ss[kk*68 + nn];
            #pragma unroll
            for (int j = 0; j < 8; j++) {
                float4 pv = *(const float4*)&ps[(cg*8+j)*68 + nn];
                acc[j] += sv.x*pv.x;
                acc[j] += sv.y*pv.y;
                acc[j] += sv.z*pv.z;
                acc[j] += sv.w*pv.w;
            }
        }
        __syncthreads();
    }
    #pragma unroll
    for (int j = 0; j < 8; j++) {
        int o = ct*64 + cg*8 + j;
        g_part[((sp*B_+b)*K_+kk)*320 + o] = acc[j];
    }
}

__global__ void k_reduce() {
    int og = blockIdx.x*256 + threadIdx.x;           // 20480 total
    int b = og / (K_*320); int rem = og % (K_*320);
    int kk = rem / 320, o = rem % 320;
    float s = 0.f;
    #pragma unroll
    for (int sp = 0; sp < 8; sp++) s += g_part[((sp*B_+b)*K_+kk)*320 + o];
    if (o < 64) g_RK[(b*K_+kk)*D_ + o] = s;
    else        g_RFV[(b*K_+kk)*C_ + (o-64)] = s;
}

// ----------------------------- k_main -----------------------------
// persistent per-(region,batch) chunk loop; q in registers via shfl broadcast.
__global__ void __launch_bounds__(256) k_main(const float* __restrict__ alpha_p,
                                              const float* __restrict__ fuse_b,
                                              const float* __restrict__ ln_g,
                                              const float* __restrict__ ln_b) {
    extern __shared__ float sm[];
    float* s_pkT = sm;                         // 64*257
    float* s_rfv = s_pkT + 64*257;             // 32*256
    float* s_rk  = s_rfv + 32*256;             // 32*65
    int*   s_pool= (int*)(s_rk + 32*65);       // 256

    int reg = blockIdx.y, b = blockIdx.z;
    int cnt = g_cnt[b*K_ + reg];
    if ((int)blockIdx.x * 64 >= cnt) return;
    int tid = threadIdx.x, lane = tid & 31, w = tid >> 5;

    if (tid < M_) s_pool[tid] = g_ti[(b*K_+reg)*M_ + tid];
    __syncthreads();
    #pragma unroll 4
    for (int i = 0; i < 64; i++) {
        int e = tid + i*256;
        int m = e >> 6, d = e & 63;
        s_pkT[d*257 + m] = g_kT[(b*N_ + s_pool[m])*D_ + d];
    }
    #pragma unroll
    for (int i = 0; i < 32; i++) s_rfv[tid + i*256] = g_RFV[b*K_*C_ + tid + i*256];
    #pragma unroll
    for (int i = 0; i < 8; i++) {
        int e = tid + i*256; int kk = e >> 6, d = e & 63;
        s_rk[kk*65+d] = g_RK[(b*K_+kk)*D_ + d];
    }
    __syncthreads();

    float a = 1.f/(1.f + expf(-alpha_p[0]));

    for (int chunk = blockIdx.x; chunk*64 < cnt; chunk += 4) {
        int base = chunk*64;
        int pend = min(base+64, cnt);
        for (int g = 0; g < 2; g++) {
            int p0 = base + w*8 + g*4;
            if (p0 >= pend) break;
            int nv = min(4, pend - p0);
            int n[4]; float q0[4], q1[4];
            #pragma unroll
            for (int i = 0; i < 4; i++) {
                if (i < nv) {
                    n[i] = g_plist[(b*K_+reg)*N_ + p0 + i];
                    q0[i] = g_qT[(b*N_+n[i])*D_ + lane];
                    q1[i] = g_qT[(b*N_+n[i])*D_ + 32 + lane];
                } else { n[i] = 0; q0[i] = 0.f; q1[i] = 0.f; }
            }

            // sims[i][mi] over the 256-entry pool; lane owns m = mi*32+lane
            float sims[4][8] = {};
            #pragma unroll
            for (int dh = 0; dh < 2; dh++) {
                #pragma unroll 2
                for (int dd = 0; dd < 32; dd++) {
                    const float* rowp = s_pkT + (dh*32+dd)*257;
                    float r8[8];
                    #pragma unroll
                    for (int mi = 0; mi < 8; mi++) r8[mi] = rowp[mi*32 + lane];
                    #pragma unroll
                    for (int i = 0; i < 4; i++) {
                        float qd = __shfl_sync(0xFFFFFFFFu, dh ? q1[i] : q0[i], dd);
                        #pragma unroll
                        for (int mi = 0; mi < 8; mi++) sims[i][mi] += qd * r8[mi];
                    }
                }
            }

            #pragma unroll 1
            for (int i = 0; i < 4; i++) {
                if (i >= nv) break;
                float sv[8];
                #pragma unroll
                for (int mi = 0; mi < 8; mi++) sv[mi] = sims[i][mi] * INVSCALE;

                // exact warp top-8 (value desc, pool index asc on ties)
                float tv[8]; int tm[8];
                unsigned used = 0;
                #pragma unroll
                for (int t = 0; t < 8; t++) {
                    float bv = -INFINITY; int bm = 1 << 30;
                    #pragma unroll
                    for (int mi = 0; mi < 8; mi++) {
                        if (!(used & (1u << mi))) {
                            float v = sv[mi]; int m = mi*32 + lane;
                            if (v > bv || (v == bv && m < bm)) { bv = v; bm = m; }
                        }
                    }
                    #pragma unroll
                    for (int off = 16; off > 0; off >>= 1) {
                        float ov = __shfl_xor_sync(0xFFFFFFFFu, bv, off);
                        int   om = __shfl_xor_sync(0xFFFFFFFFu, bm, off);
                        if (ov > bv || (ov == bv && om < bm)) { bv = ov; bm = om; }
                    }
                    tv[t] = bv; tm[t] = bm;
                    if ((bm & 31) == lane) used |= 1u << (bm >> 5);
                }
                float ww[8], wsum = 0.f;
                #pragma unroll
                for (int t = 0; t < 8; t++) { ww[t] = expf(tv[t] - tv[0]); wsum += ww[t]; }
                float winv = 1.f/wsum;
                // sparse branch: gather fv rows
                float fs[8] = {};
                #pragma unroll
                for (int t = 0; t < 8; t++) {
                    float att = ww[t]*winv;
                    int gidx = s_pool[tm[t]];
                    const float* fvrow = g_fvT + (b*N_ + gidx)*C_;
                    #pragma unroll
                    for (int j = 0; j < 8; j++) fs[j] += att * fvrow[j*32 + lane];
                }
                // dense branch: logit for region k = lane
                float lg = 0.f;
                #pragma unroll
                for (int dh = 0; dh < 2; dh++) {
                    #pragma unroll 4
                    for (int dd = 0; dd < 32; dd++) {
                        float qd = __shfl_sync(0xFFFFFFFFu, dh ? q1[i] : q0[i], dd);
                        lg += qd * s_rk[lane*65 + dh*32 + dd];
                    }
                }
                lg *= INVSCALE;
                float mx = lg;
                #pragma unroll
                for (int off = 16; off > 0; off >>= 1)
                    mx = fmaxf(mx, __shfl_xor_sync(0xFFFFFFFFu, mx, off));
                float ev = expf(lg - mx), es = ev;
                #pragma unroll
                for (int off = 16; off > 0; off >>= 1) es += __shfl_xor_sync(0xFFFFFFFFu, es, off);
                float attn = ev/es;
                float fc[8] = {};
                #pragma unroll 4
                for (int kk = 0; kk < K_; kk++) {
                    float ak = __shfl_sync(0xFFFFFFFFu, attn, kk);
                    const float* rrow = s_rfv + kk*256;
                    #pragma unroll
                    for (int j = 0; j < 8; j++) fc[j] += ak * rrow[j*32 + lane];
                }
                // combine + fuse bias + residual + channel LayerNorm
                float pre[8], sum = 0.f, sq = 0.f;
                const float* xrow = g_xT + (b*N_+n[i])*C_;
                #pragma unroll
                for (int j = 0; j < 8; j++) {
                    int c = j*32 + lane;
                    float f = a*fc[j] + (1.f - a)*fs[j] + fuse_b[c];
                    float v = xrow[c] + f;
                    pre[j] = v; sum += v; sq += v*v;
                }
                #pragma unroll
                for (int off = 16; off > 0; off >>= 1) {
                    sum += __shfl_xor_sync(0xFFFFFFFFu, sum, off);
                    sq  += __shfl_xor_sync(0xFFFFFFFFu, sq,  off);
                }
                float mu = sum * (1.f/256.f);
                float var = sq * (1.f/256.f) - mu*mu;
                float rstd = rsqrtf(var + 1e-5f);
                float* orow = g_outT + (b*N_+n[i])*C_;
                #pragma unroll
                for (int j = 0; j < 8; j++) {
                    int c = j*32 + lane;
                    orow[c] = (pre[j]-mu)*rstd*ln_g[c] + ln_b[c];
                }
            }
        }
    }
}

// ----------------------------- launch -----------------------------
extern "C" void kernel_launch(void* const* d_in, const int* in_sizes, int n_in,
                              void* d_out, int out_size) {
    const float* x      = (const float*)d_in[0];
    const float* sem_w  = (const float*)d_in[1];
    const float* sem_b  = (const float*)d_in[2];
    const float* q_w    = (const float*)d_in[3];
    const float* k_w    = (const float*)d_in[4];
    const float* v_w    = (const float*)d_in[5];
    const float* fuse_w = (const float*)d_in[6];
    const float* fuse_b = (const float*)d_in[7];
    const float* alpha  = (const float*)d_in[8];
    const float* ln_g   = (const float*)d_in[9];
    const float* ln_b   = (const float*)d_in[10];
    float* out = (float*)d_out;

    const int SMEM_MAIN = (64*257 + 32*256 + 32*65)*4 + 256*4;
    cudaFuncSetAttribute((const void*)k_main,
                         cudaFuncAttributeMaxDynamicSharedMemorySize, SMEM_MAIN);

    k_prep<<<26, 256>>>(sem_w, sem_b, q_w, k_w, v_w, fuse_w);
    k_gemm<<<dim3(32, 7, B_), 256>>>(x);
    k_sem<<<128, 64>>>();
    k_sel<<<B_*K_, 256>>>();
    k_transpA<<<dim3(128, 20, B_), dim3(32, 8)>>>(x);
    k_region<<<dim3(5, 8, B_), 256>>>();
    k_reduce<<<80, 256>>>();
    k_main<<<dim3(4, K_, B_), 256, SMEM_MAIN>>>(alpha, fuse_b, ln_g, ln_b);
    k_transpO<<<dim3(8, 128, B_), dim3(32, 8)>>>(out);
}

// round 6
// speedup vs baseline: 1.2518x; 1.0286x over previous
#include <cuda_runtime.h>
#include <cuda_bf16.h>
#include <math.h>

#define B_ 2
#define C_ 256
#define N_ 4096
#define D_ 64
#define K_ 32
#define M_ 256
#define R_ 416
#define RP2 512
#define INVSCALE (1.0f/8.000001f)
typedef unsigned long long ull;
typedef unsigned int uint;

// ----------------------------- scratch -----------------------------
__device__ __align__(16) __nv_bfloat16 g_Wh[RP2*C_];
__device__ __align__(16) __nv_bfloat16 g_Wl[RP2*C_];
__device__ __align__(16) __nv_bfloat16 g_xh[B_*C_*N_];
__device__ __align__(16) __nv_bfloat16 g_xl[B_*C_*N_];
__device__ float g_bias[R_];
__device__ float g_P[B_*R_*N_];        // [sem(32); q(64); k(64); fv(256)] x N
__device__ float g_sem[B_*K_*N_];
__device__ int   g_ti[B_*K_*M_];
__device__ int   g_cnt[B_*K_];
__device__ int   g_plist[B_*K_*N_];
__device__ float g_qT[B_*N_*D_];
__device__ float g_kT[B_*N_*D_];
__device__ float g_fvT[B_*N_*C_];
__device__ float g_xT[B_*N_*C_];
__device__ float g_part[8*B_*K_*320];
__device__ float g_RK[B_*K_*D_];
__device__ float g_RFV[B_*K_*C_];
__device__ float g_outT[B_*N_*C_];

__device__ __forceinline__ void split_bf16(float v, __nv_bfloat16& h, __nv_bfloat16& l) {
    h = __float2bfloat16_rn(v);
    l = __float2bfloat16_rn(v - __bfloat162float(h));
}

// ----------------------------- k_cvtx -----------------------------
// x (fp32) -> bf16 hi/lo, same [b][c][n] layout
__global__ void __launch_bounds__(256) k_cvtx(const float* __restrict__ x) {
    int i = (blockIdx.x*256 + threadIdx.x)*4;
    float4 v = *(const float4*)&x[i];
    __nv_bfloat16 h[4], l[4];
    split_bf16(v.x, h[0], l[0]); split_bf16(v.y, h[1], l[1]);
    split_bf16(v.z, h[2], l[2]); split_bf16(v.w, h[3], l[3]);
    uint hw0 = (uint)__bfloat16_as_ushort(h[0]) | ((uint)__bfloat16_as_ushort(h[1]) << 16);
    uint hw1 = (uint)__bfloat16_as_ushort(h[2]) | ((uint)__bfloat16_as_ushort(h[3]) << 16);
    uint lw0 = (uint)__bfloat16_as_ushort(l[0]) | ((uint)__bfloat16_as_ushort(l[1]) << 16);
    uint lw1 = (uint)__bfloat16_as_ushort(l[2]) | ((uint)__bfloat16_as_ushort(l[3]) << 16);
    *(uint2*)&g_xh[i] = make_uint2(hw0, hw1);
    *(uint2*)&g_xl[i] = make_uint2(lw0, lw1);
}

// ----------------------------- k_zero -----------------------------
// zero W pad rows [416,512) and region counters
__global__ void k_zero() {
    int w = blockIdx.x*256 + threadIdx.x;       // 48*256 = 12288 words
    ((uint*)g_Wh)[53248 + w] = 0;
    ((uint*)g_Wl)[53248 + w] = 0;
    if (blockIdx.x == 0 && threadIdx.x < B_*K_) g_cnt[threadIdx.x] = 0;
}

// ----------------------------- k_prep -----------------------------
// blocks 0..9: copy sem/q/k rows (16 each); blocks 10..41: fv = fuse_w @ v_w (8 rows each)
__global__ void __launch_bounds__(256) k_prep(
    const float* __restrict__ sem_w, const float* __restrict__ sem_b,
    const float* __restrict__ q_w,  const float* __restrict__ k_w,
    const float* __restrict__ v_w,  const float* __restrict__ fuse_w) {
    int blk = blockIdx.x, tid = threadIdx.x;
    if (blk < 10) {
        #pragma unroll
        for (int it = 0; it < 16; it++) {
            int e = tid + it*256;
            int r = blk*16 + (e >> 8), c = e & 255;
            float val = (r < 32) ? sem_w[r*C_ + c]
                      : (r < 96) ? q_w[(r-32)*C_ + c]
                                 : k_w[(r-96)*C_ + c];
            __nv_bfloat16 h, l; split_bf16(val, h, l);
            g_Wh[r*C_ + c] = h; g_Wl[r*C_ + c] = l;
            if (c == 0) g_bias[r] = (r < 32) ? sem_b[r] : 0.f;
        }
    } else {
        int r0 = 160 + (blk-10)*8;
        __shared__ float fw[8*256];
        #pragma unroll
        for (int it = 0; it < 8; it++) {
            int e = tid + it*256;
            fw[e] = fuse_w[(r0-160)*C_ + e];
        }
        __syncthreads();
        float acc[8] = {};
        for (int m = 0; m < C_; m++) {
            float v = v_w[m*C_ + tid];
            #pragma unroll
            for (int rr = 0; rr < 8; rr++) acc[rr] += fw[rr*256 + m] * v;
        }
        #pragma unroll
        for (int rr = 0; rr < 8; rr++) {
            int r = r0 + rr;
            __nv_bfloat16 h, l; split_bf16(acc[rr], h, l);
            g_Wh[r*C_ + tid] = h; g_Wl[r*C_ + tid] = l;
            if (tid == 0) g_bias[r] = 0.f;
        }
    }
}

// ----------------------------- k_gemm (bf16-split tensor core) -----------------------------
// P = W @ x + bias, computed as Wh·xh + Wh·xl + Wl·xh in fp32 accum.
// Block tile 128r x 128n, BK=32, 8 warps (4m x 2n), warp tile 32x64, mma m16n8k16.
__device__ __forceinline__ void mma16816(float* d, const uint* a, uint b0, uint b1) {
    asm volatile(
        "mma.sync.aligned.m16n8k16.row.col.f32.bf16.bf16.f32 "
        "{%0,%1,%2,%3}, {%4,%5,%6,%7}, {%8,%9}, {%0,%1,%2,%3};"
        : "+f"(d[0]), "+f"(d[1]), "+f"(d[2]), "+f"(d[3])
        : "r"(a[0]), "r"(a[1]), "r"(a[2]), "r"(a[3]), "r"(b0), "r"(b1));
}

__global__ void __launch_bounds__(256) k_gemm() {
    __shared__ __nv_bfloat16 As[2][128][40];   // [h/l][r][k], stride 40 (conflict-free, 16B-aligned)
    __shared__ uint Bs2[2][16][136];           // [h/l][kpair][n] packed (k,k+1)

    int n0 = blockIdx.x*128, r0 = blockIdx.y*128, b = blockIdx.z;
    int tid = threadIdx.x, lane = tid & 31, wid = tid >> 5;
    int wm = wid & 3, wn = wid >> 2;
    const __nv_bfloat16* xh = g_xh + b*C_*N_;
    const __nv_bfloat16* xl = g_xl + b*C_*N_;

    float acc[2][8][4];
    #pragma unroll
    for (int mt = 0; mt < 2; mt++)
        #pragma unroll
        for (int nt = 0; nt < 8; nt++)
            #pragma unroll
            for (int i = 0; i < 4; i++) acc[mt][nt][i] = 0.f;

    for (int kt = 0; kt < 8; kt++) {
        int kc = kt*32;
        // stage A (both hi/lo): 128 rows x 32 k
        #pragma unroll
        for (int i = 0; i < 2; i++) {
            int e = tid + i*256;
            int r = e >> 2, c8 = (e & 3)*8;
            *(uint4*)&As[0][r][c8] = *(const uint4*)&g_Wh[(r0 + r)*C_ + kc + c8];
            *(uint4*)&As[1][r][c8] = *(const uint4*)&g_Wl[(r0 + r)*C_ + kc + c8];
        }
        // stage B (both hi/lo): pack k-pairs
        {
            int kp = tid >> 4, n8 = (tid & 15)*8;
            uint4 a0 = *(const uint4*)&xh[(kc + 2*kp)*N_ + n0 + n8];
            uint4 a1 = *(const uint4*)&xh[(kc + 2*kp + 1)*N_ + n0 + n8];
            uint4 o0 = make_uint4(__byte_perm(a0.x, a1.x, 0x5410), __byte_perm(a0.x, a1.x, 0x7632),
                                  __byte_perm(a0.y, a1.y, 0x5410), __byte_perm(a0.y, a1.y, 0x7632));
            uint4 o1 = make_uint4(__byte_perm(a0.z, a1.z, 0x5410), __byte_perm(a0.z, a1.z, 0x7632),
                                  __byte_perm(a0.w, a1.w, 0x5410), __byte_perm(a0.w, a1.w, 0x7632));
            *(uint4*)&Bs2[0][kp][n8]   = o0;
            *(uint4*)&Bs2[0][kp][n8+4] = o1;
            uint4 c0 = *(const uint4*)&xl[(kc + 2*kp)*N_ + n0 + n8];
            uint4 c1 = *(const uint4*)&xl[(kc + 2*kp + 1)*N_ + n0 + n8];
            uint4 p0 = make_uint4(__byte_perm(c0.x, c1.x, 0x5410), __byte_perm(c0.x, c1.x, 0x7632),
                                  __byte_perm(c0.y, c1.y, 0x5410), __byte_perm(c0.y, c1.y, 0x7632));
            uint4 p1 = make_uint4(__byte_perm(c0.z, c1.z, 0x5410), __byte_perm(c0.z, c1.z, 0x7632),
                                  __byte_perm(c0.w, c1.w, 0x5410), __byte_perm(c0.w, c1.w, 0x7632));
            *(uint4*)&Bs2[1][kp][n8]   = p0;
            *(uint4*)&Bs2[1][kp][n8+4] = p1;
        }
        __syncthreads();

        #pragma unroll
        for (int seg = 0; seg < 3; seg++) {
            const uint* A32 = (const uint*)As[seg < 2 ? 0 : 1];
            const uint (*B2)[136] = Bs2[seg == 1 ? 1 : 0];
            #pragma unroll
            for (int k16 = 0; k16 < 2; k16++) {
                uint a[2][4];
                #pragma unroll
                for (int mt = 0; mt < 2; mt++) {
                    int rA = wm*32 + mt*16 + (lane >> 2);
                    int kw = k16*8 + (lane & 3);
                    a[mt][0] = A32[rA*20 + kw];
                    a[mt][1] = A32[(rA+8)*20 + kw];
                    a[mt][2] = A32[rA*20 + kw + 4];
                    a[mt][3] = A32[(rA+8)*20 + kw + 4];
                }
                int kp = k16*8 + (lane & 3);
                #pragma unroll
                for (int nt = 0; nt < 8; nt++) {
                    int nn = wn*64 + nt*8 + (lane >> 2);
                    uint b0 = B2[kp][nn];
                    uint b1 = B2[kp+4][nn];
                    mma16816(acc[0][nt], a[0], b0, b1);
                    mma16816(acc[1][nt], a[1], b0, b1);
                }
            }
        }
        __syncthreads();
    }

    // epilogue: add bias, store
    #pragma unroll
    for (int mt = 0; mt < 2; mt++) {
        int r = r0 + wm*32 + mt*16 + (lane >> 2);
        #pragma unroll
        for (int nt = 0; nt < 8; nt++) {
            int n = n0 + wn*64 + nt*8 + (lane & 3)*2;
            if (r < R_) {
                float bi = g_bias[r];
                *(float2*)&g_P[(b*R_ + r)*N_ + n] =
                    make_float2(acc[mt][nt][0] + bi, acc[mt][nt][1] + bi);
            }
            if (r + 8 < R_) {
                float bi2 = g_bias[r + 8];
                *(float2*)&g_P[(b*R_ + r + 8)*N_ + n] =
                    make_float2(acc[mt][nt][2] + bi2, acc[mt][nt][3] + bi2);
            }
        }
    }
}

// ----------------------------- k_sem -----------------------------
// 4 threads per position (8 k's each), quad-shfl combine.
__global__ void __launch_bounds__(256) k_sem() {
    int g = blockIdx.x*256 + threadIdx.x;      // 32768 = 8192 pos * 4
    int pos = g >> 2, s = g & 3;
    int b = pos >> 12, n = pos & (N_-1);
    float l[8];
    float mx = -INFINITY; int am = K_;
    #pragma unroll
    for (int j = 0; j < 8; j++) {
        l[j] = g_P[(b*R_ + s*8 + j)*N_ + n];
        if (l[j] > mx) { mx = l[j]; am = s*8 + j; }
    }
    #pragma unroll
    for (int off = 1; off <= 2; off <<= 1) {
        float ov = __shfl_xor_sync(0xFFFFFFFFu, mx, off);
        int   oa = __shfl_xor_sync(0xFFFFFFFFu, am, off);
        if (ov > mx || (ov == mx && oa < am)) { mx = ov; am = oa; }
    }
    float sum = 0.f;
    #pragma unroll
    for (int j = 0; j < 8; j++) { l[j] = expf(l[j] - mx); sum += l[j]; }
    #pragma unroll
    for (int off = 1; off <= 2; off <<= 1)
        sum += __shfl_xor_sync(0xFFFFFFFFu, sum, off);
    float inv = 1.f/sum;
    #pragma unroll
    for (int j = 0; j < 8; j++) g_sem[(b*K_ + s*8 + j)*N_ + n] = l[j]*inv;
    if (s == 0) {
        int slot = atomicAdd(&g_cnt[b*K_ + am], 1);
        g_plist[(b*K_+am)*N_ + slot] = n;
    }
}

// ----------------------------- k_sel -----------------------------
// exact top-256 per (b,k): 12-bit histogram select + boundary sort; parallel suffix scans.
__global__ void __launch_bounds__(256) k_sel() {
    __shared__ ull cand[4096];                     // first 16 KB aliased as hist
    __shared__ ull win[256];
    __shared__ int sufc[256];
    __shared__ int s_tc, s_cA, s_t, s_A, s_nw, s_nc;
    unsigned* hist = (unsigned*)cand;

    int bk = blockIdx.x; int b = bk >> 5, k = bk & 31;
    int tid = threadIdx.x;
    const float* row = g_sem + (b*K_ + k)*N_;

    for (int i = tid; i < 4096; i += 256) hist[i] = 0;
    __syncthreads();

    unsigned vb[16];
    #pragma unroll
    for (int j = 0; j < 16; j++) {
        vb[j] = __float_as_uint(row[tid + j*256]);
        atomicAdd(&hist[vb[j] >> 20], 1);
    }
    __syncthreads();

    int cs = 0;
    #pragma unroll
    for (int h = 0; h < 16; h++) cs += hist[tid*16 + h];
    sufc[tid] = cs;
    __syncthreads();
    // suffix scan (Hillis-Steele)
    #pragma unroll
    for (int st = 1; st < 256; st <<= 1) {
        int add = (tid + st < 256) ? sufc[tid + st] : 0;
        __syncthreads();
        sufc[tid] += add;
        __syncthreads();
    }
    int nxt = (tid < 255) ? sufc[tid + 1] : 0;
    if (sufc[tid] >= M_ && nxt < M_) { s_tc = tid; s_cA = nxt; }
    if (tid == 0) { s_nw = 0; s_nc = 0; }
    __syncthreads();
    int tc = s_tc, cA = s_cA;
    if (tid < 16) {
        int sg = 0;
        for (int j = tid; j < 16; j++) sg += hist[tc*16 + j];
        int hi = hist[tc*16 + tid];
        if (cA + sg >= M_ && cA + sg - hi < M_) { s_t = tc*16 + tid; s_A = cA + sg - hi; }
    }
    __syncthreads();
    int t = s_t, A = s_A, s = M_ - A;
    __syncthreads();   // hist reads done; cand may be overwritten now

    #pragma unroll
    for (int j = 0; j < 16; j++) {
        unsigned v = vb[j];
        int idx = tid + j*256;
        unsigned bkt = v >> 20;
        ull key = ((ull)v << 32) | (unsigned)(0xFFFFFFFFu - (unsigned)idx);
        if ((int)bkt > t) { int p = atomicAdd(&s_nw, 1); win[p] = ~key; }
        else if ((int)bkt == t) { int p = atomicAdd(&s_nc, 1); cand[p] = ~key; }
    }
    __syncthreads();

    int nc = s_nc;
    int P = 1; while (P < nc) P <<= 1;
    for (int i = tid; i < P; i += 256) if (i >= nc) cand[i] = 0xFFFFFFFFFFFFFFFFULL;
    __syncthreads();
    for (int sz = 2; sz <= P; sz <<= 1) {
        for (int str = sz >> 1; str > 0; str >>= 1) {
            for (int i = tid; i < P; i += 256) {
                int l = i ^ str;
                if (l > i) {
                    ull a = cand[i], c2 = cand[l];
                    bool up = ((i & sz) == 0);
                    if ((a > c2) == up) { cand[i] = c2; cand[l] = a; }
                }
            }
            __syncthreads();
        }
    }
    for (int i = tid; i < s; i += 256) win[A + i] = cand[i];
    __syncthreads();
    for (int sz = 2; sz <= 256; sz <<= 1) {
        for (int str = sz >> 1; str > 0; str >>= 1) {
            int i = tid, l = i ^ str;
            if (l > i) {
                ull a = win[i], c2 = win[l];
                bool up = ((i & sz) == 0);
                if ((a > c2) == up) { win[i] = c2; win[l] = a; }
            }
            __syncthreads();
        }
    }
    g_ti[(b*K_ + k)*M_ + tid] = (int)(unsigned)(win[tid] & 0xFFFFFFFFu);
}

// ----------------------------- transposes -----------------------------
__global__ void k_transpA(const float* __restrict__ x) {
    __shared__ float t[32][33];
    int b = blockIdx.z, x0 = blockIdx.x*32, y = blockIdx.y;
    const float* src; float* dst; int r0, Rr;
    if      (y < 2)  { src = g_P + (b*R_ + 32)*N_;  dst = g_qT  + b*N_*D_; r0 = y*32;       Rr = D_; }
    else if (y < 4)  { src = g_P + (b*R_ + 96)*N_;  dst = g_kT  + b*N_*D_; r0 = (y-2)*32;   Rr = D_; }
    else if (y < 12) { src = g_P + (b*R_ + 160)*N_; dst = g_fvT + b*N_*C_; r0 = (y-4)*32;   Rr = C_; }
    else             { src = x + b*C_*N_;           dst = g_xT  + b*N_*C_; r0 = (y-12)*32;  Rr = C_; }
    int tx = threadIdx.x, ty = threadIdx.y;
    #pragma unroll
    for (int i = 0; i < 32; i += 8)
        t[ty+i][tx] = src[(r0 + ty + i)*N_ + x0 + tx];
    __syncthreads();
    #pragma unroll
    for (int i = 0; i < 32; i += 8)
        dst[(x0 + ty + i)*Rr + r0 + tx] = t[tx][ty+i];
}

__global__ void k_transpO(float* __restrict__ out) {
    __shared__ float t[32][33];
    int b = blockIdx.z, c0 = blockIdx.x*32, n0 = blockIdx.y*32;
    int tx = threadIdx.x, ty = threadIdx.y;
    #pragma unroll
    for (int i = 0; i < 32; i += 8)
        t[ty+i][tx] = g_outT[b*N_*C_ + (n0 + ty + i)*C_ + c0 + tx];
    __syncthreads();
    #pragma unroll
    for (int i = 0; i < 32; i += 8)
        out[b*C_*N_ + (c0 + ty + i)*N_ + n0 + tx] = t[tx][ty+i];
}

// ----------------------------- k_region -----------------------------
__global__ void __launch_bounds__(256) k_region() {
    __shared__ float ss[32*68];
    __shared__ float ps[64*68];
    int ct = blockIdx.x, sp = blockIdx.y, b = blockIdx.z;
    int tid = threadIdx.x;
    int kk = tid & 31, cg = tid >> 5;
    float acc[8] = {};
    for (int nch = 0; nch < 8; nch++) {
        int nn0 = sp*512 + nch*64;
        #pragma unroll
        for (int i = 0; i < 8; i++) {
            int e = tid + i*256; int kr = e >> 6, nn = e & 63;
            ss[kr*68+nn] = g_sem[(b*K_+kr)*N_ + nn0 + nn];
        }
        #pragma unroll
        for (int i = 0; i < 16; i++) {
            int e = tid + i*256; int c = e >> 6, nn = e & 63;
            ps[c*68+nn] = g_P[(b*R_ + 96 + ct*64 + c)*N_ + nn0 + nn];
        }
        __syncthreads();
        #pragma unroll 4
        for (int nn = 0; nn < 64; nn += 4) {
            float4 sv = *(const float4*)&ss[kk*68 + nn];
            #pragma unroll
            for (int j = 0; j < 8; j++) {
                float4 pv = *(const float4*)&ps[(cg*8+j)*68 + nn];
                acc[j] += sv.x*pv.x;
                acc[j] += sv.y*pv.y;
                acc[j] += sv.z*pv.z;
                acc[j] += sv.w*pv.w;
            }
        }
        __syncthreads();
    }
    #pragma unroll
    for (int j = 0; j < 8; j++) {
        int o = ct*64 + cg*8 + j;
        g_part[((sp*B_+b)*K_+kk)*320 + o] = acc[j];
    }
}

__global__ void k_reduce() {
    int og = blockIdx.x*256 + threadIdx.x;
    int b = og / (K_*320); int rem = og % (K_*320);
    int kk = rem / 320, o = rem % 320;
    float s = 0.f;
    #pragma unroll
    for (int sp = 0; sp < 8; sp++) s += g_part[((sp*B_+b)*K_+kk)*320 + o];
    if (o < 64) g_RK[(b*K_+kk)*D_ + o] = s;
    else        g_RFV[(b*K_+kk)*C_ + (o-64)] = s;
}

// ----------------------------- k_main -----------------------------
__global__ void __launch_bounds__(256) k_main(const float* __restrict__ alpha_p,
                                              const float* __restrict__ fuse_b,
                                              const float* __restrict__ ln_g,
                                              const float* __restrict__ ln_b) {
    extern __shared__ float sm[];
    float* s_pkT = sm;                         // 64*257
    float* s_rfv = s_pkT + 64*257;             // 32*256
    float* s_rk  = s_rfv + 32*256;             // 32*65
    int*   s_pool= (int*)(s_rk + 32*65);       // 256

    int reg = blockIdx.y, b = blockIdx.z;
    int cnt = g_cnt[b*K_ + reg];
    if ((int)blockIdx.x * 64 >= cnt) return;
    int tid = threadIdx.x, lane = tid & 31, w = tid >> 5;

    if (tid < M_) s_pool[tid] = g_ti[(b*K_+reg)*M_ + tid];
    __syncthreads();
    #pragma unroll 4
    for (int i = 0; i < 64; i++) {
        int e = tid + i*256;
        int m = e >> 6, d = e & 63;
        s_pkT[d*257 + m] = g_kT[(b*N_ + s_pool[m])*D_ + d];
    }
    #pragma unroll
    for (int i = 0; i < 32; i++) s_rfv[tid + i*256] = g_RFV[b*K_*C_ + tid + i*256];
    #pragma unroll
    for (int i = 0; i < 8; i++) {
        int e = tid + i*256; int kk = e >> 6, d = e & 63;
        s_rk[kk*65+d] = g_RK[(b*K_+kk)*D_ + d];
    }
    __syncthreads();

    float a = 1.f/(1.f + expf(-alpha_p[0]));

    for (int chunk = blockIdx.x; chunk*64 < cnt; chunk += 4) {
        int base = chunk*64;
        int pend = min(base+64, cnt);
        for (int g = 0; g < 2; g++) {
            int p0 = base + w*8 + g*4;
            if (p0 >= pend) break;
            int nv = min(4, pend - p0);
            int n[4]; float q0[4], q1[4];
            #pragma unroll
            for (int i = 0; i < 4; i++) {
                if (i < nv) {
                    n[i] = g_plist[(b*K_+reg)*N_ + p0 + i];
                    q0[i] = g_qT[(b*N_+n[i])*D_ + lane];
                    q1[i] = g_qT[(b*N_+n[i])*D_ + 32 + lane];
                } else { n[i] = 0; q0[i] = 0.f; q1[i] = 0.f; }
            }

            float sims[4][8] = {};
            #pragma unroll
            for (int dh = 0; dh < 2; dh++) {
                #pragma unroll 2
                for (int dd = 0; dd < 32; dd++) {
                    const float* rowp = s_pkT + (dh*32+dd)*257;
                    float r8[8];
                    #pragma unroll
                    for (int mi = 0; mi < 8; mi++) r8[mi] = rowp[mi*32 + lane];
                    #pragma unroll
                    for (int i = 0; i < 4; i++) {
                        float qd = __shfl_sync(0xFFFFFFFFu, dh ? q1[i] : q0[i], dd);
                        #pragma unroll
                        for (int mi = 0; mi < 8; mi++) sims[i][mi] += qd * r8[mi];
                    }
                }
            }

            #pragma unroll 1
            for (int i = 0; i < 4; i++) {
                if (i >= nv) break;
                float sv[8];
                #pragma unroll
                for (int mi = 0; mi < 8; mi++) sv[mi] = sims[i][mi] * INVSCALE;

                float tv[8]; int tm[8];
                unsigned used = 0;
                #pragma unroll
                for (int t = 0; t < 8; t++) {
                    float bv = -INFINITY; int bm = 1 << 30;
                    #pragma unroll
                    for (int mi = 0; mi < 8; mi++) {
                        if (!(used & (1u << mi))) {
                            float v = sv[mi]; int m = mi*32 + lane;
                            if (v > bv || (v == bv && m < bm)) { bv = v; bm = m; }
                        }
                    }
                    #pragma unroll
                    for (int off = 16; off > 0; off >>= 1) {
                        float ov = __shfl_xor_sync(0xFFFFFFFFu, bv, off);
                        int   om = __shfl_xor_sync(0xFFFFFFFFu, bm, off);
                        if (ov > bv || (ov == bv && om < bm)) { bv = ov; bm = om; }
                    }
                    tv[t] = bv; tm[t] = bm;
                    if ((bm & 31) == lane) used |= 1u << (bm >> 5);
                }
                float ww[8], wsum = 0.f;
                #pragma unroll
                for (int t = 0; t < 8; t++) { ww[t] = expf(tv[t] - tv[0]); wsum += ww[t]; }
                float winv = 1.f/wsum;
                float fs[8] = {};
                #pragma unroll
                for (int t = 0; t < 8; t++) {
                    float att = ww[t]*winv;
                    int gidx = s_pool[tm[t]];
                    const float* fvrow = g_fvT + (b*N_ + gidx)*C_;
                    #pragma unroll
                    for (int j = 0; j < 8; j++) fs[j] += att * fvrow[j*32 + lane];
                }
                float lg = 0.f;
                #pragma unroll
                for (int dh = 0; dh < 2; dh++) {
                    #pragma unroll 4
                    for (int dd = 0; dd < 32; dd++) {
                        float qd = __shfl_sync(0xFFFFFFFFu, dh ? q1[i] : q0[i], dd);
                        lg += qd * s_rk[lane*65 + dh*32 + dd];
                    }
                }
                lg *= INVSCALE;
                float mx = lg;
                #pragma unroll
                for (int off = 16; off > 0; off >>= 1)
                    mx = fmaxf(mx, __shfl_xor_sync(0xFFFFFFFFu, mx, off));
                float ev = expf(lg - mx), es = ev;
                #pragma unroll
                for (int off = 16; off > 0; off >>= 1) es += __shfl_xor_sync(0xFFFFFFFFu, es, off);
                float attn = ev/es;
                float fc[8] = {};
                #pragma unroll 4
                for (int kk = 0; kk < K_; kk++) {
                    float ak = __shfl_sync(0xFFFFFFFFu, attn, kk);
                    const float* rrow = s_rfv + kk*256;
                    #pragma unroll
                    for (int j = 0; j < 8; j++) fc[j] += ak * rrow[j*32 + lane];
                }
                float pre[8], sum = 0.f, sq = 0.f;
                const float* xrow = g_xT + (b*N_+n[i])*C_;
                #pragma unroll
                for (int j = 0; j < 8; j++) {
                    int c = j*32 + lane;
                    float f = a*fc[j] + (1.f - a)*fs[j] + fuse_b[c];
                    float v = xrow[c] + f;
                    pre[j] = v; sum += v; sq += v*v;
                }
                #pragma unroll
                for (int off = 16; off > 0; off >>= 1) {
                    sum += __shfl_xor_sync(0xFFFFFFFFu, sum, off);
                    sq  += __shfl_xor_sync(0xFFFFFFFFu, sq,  off);
                }
                float mu = sum * (1.f/256.f);
                float var = sq * (1.f/256.f) - mu*mu;
                float rstd = rsqrtf(var + 1e-5f);
                float* orow = g_outT + (b*N_+n[i])*C_;
                #pragma unroll
                for (int j = 0; j < 8; j++) {
                    int c = j*32 + lane;
                    orow[c] = (pre[j]-mu)*rstd*ln_g[c] + ln_b[c];
                }
            }
        }
    }
}

// ----------------------------- launch -----------------------------
extern "C" void kernel_launch(void* const* d_in, const int* in_sizes, int n_in,
                              void* d_out, int out_size) {
    const float* x      = (const float*)d_in[0];
    const float* sem_w  = (const float*)d_in[1];
    const float* sem_b  = (const float*)d_in[2];
    const float* q_w    = (const float*)d_in[3];
    const float* k_w    = (const float*)d_in[4];
    const float* v_w    = (const float*)d_in[5];
    const float* fuse_w = (const float*)d_in[6];
    const float* fuse_b = (const float*)d_in[7];
    const float* alpha  = (const float*)d_in[8];
    const float* ln_g   = (const float*)d_in[9];
    const float* ln_b   = (const float*)d_in[10];
    float* out = (float*)d_out;

    const int SMEM_MAIN = (64*257 + 32*256 + 32*65)*4 + 256*4;
    cudaFuncSetAttribute((const void*)k_main,
                         cudaFuncAttributeMaxDynamicSharedMemorySize, SMEM_MAIN);

    k_cvtx<<<2048, 256>>>(x);                              // #1
    k_prep<<<42, 256>>>(sem_w, sem_b, q_w, k_w, v_w, fuse_w); // #2
    k_zero<<<48, 256>>>();                                 // #3
    k_gemm<<<dim3(32, 4, B_), 256>>>();                    // #4  <- ncu slot
    k_sem<<<128, 256>>>();                                 // #5
    k_sel<<<B_*K_, 256>>>();                               // #6
    k_transpA<<<dim3(128, 20, B_), dim3(32, 8)>>>(x);      // #7
    k_region<<<dim3(5, 8, B_), 256>>>();                   // #8
    k_reduce<<<80, 256>>>();                               // #9
    k_main<<<dim3(4, K_, B_), 256, SMEM_MAIN>>>(alpha, fuse_b, ln_g, ln_b); // #10
    k_transpO<<<dim3(8, 128, B_), dim3(32, 8)>>>(out);     // #11
}

// round 7
// speedup vs baseline: 1.3731x; 1.0969x over previous
#include <cuda_runtime.h>
#include <cuda_bf16.h>
#include <math.h>

#define B_ 2
#define C_ 256
#define N_ 4096
#define D_ 64
#define K_ 32
#define M_ 256
#define R_ 416
#define RP2 512
#define INVSCALE (1.0f/8.000001f)
typedef unsigned long long ull;
typedef unsigned int uint;

// ----------------------------- scratch -----------------------------
__device__ __align__(16) __nv_bfloat16 g_Wh[RP2*C_];
__device__ __align__(16) __nv_bfloat16 g_Wl[RP2*C_];
__device__ __align__(16) __nv_bfloat16 g_xh[B_*C_*N_];
__device__ __align__(16) __nv_bfloat16 g_xl[B_*C_*N_];
__device__ float g_bias[R_];
__device__ float g_P[B_*R_*N_];        // [sem(32); q(64); k(64); fv(256)] x N
__device__ float g_sem[B_*K_*N_];
__device__ int   g_ti[B_*K_*M_];
__device__ int   g_cnt[B_*K_];
__device__ int   g_plist[B_*K_*N_];
__device__ float g_qT[B_*N_*D_];
__device__ float g_kT[B_*N_*D_];
__device__ float g_fvT[B_*N_*C_];
__device__ float g_xT[B_*N_*C_];
__device__ float g_RK[B_*K_*D_];
__device__ float g_RFV[B_*K_*C_];
__device__ float g_outT[B_*N_*C_];

__device__ __forceinline__ void split_bf16(float v, __nv_bfloat16& h, __nv_bfloat16& l) {
    h = __float2bfloat16_rn(v);
    l = __float2bfloat16_rn(v - __bfloat162float(h));
}
__device__ __forceinline__ uint cvta_smem(const void* p) {
    return (uint)__cvta_generic_to_shared(p);
}

// ----------------------------- k_zero -----------------------------
// zero W pad rows [416,512), region counters, RK/RFV accumulators
__global__ void k_zero() {
    int w = blockIdx.x*256 + threadIdx.x;       // 48*256 = 12288
    ((uint*)g_Wh)[53248 + w] = 0;
    ((uint*)g_Wl)[53248 + w] = 0;
    if (w < 4096) ((float*)g_RK)[w] = 0.f;      // 2*32*64
    if (w < 8192) { g_RFV[w] = 0.f; g_RFV[w + 8192] = 0.f; }
    if (blockIdx.x == 0 && threadIdx.x < B_*K_) g_cnt[threadIdx.x] = 0;
}

// ----------------------------- k_cvtx -----------------------------
// x (fp32) -> bf16 hi/lo (same layout) + xT (position-major), one pass over x.
// grid (64, 8, B), block (32,8): tile 32c x 64n
__global__ void __launch_bounds__(256) k_cvtx(const float* __restrict__ x) {
    __shared__ float t[64][33];                 // [n-local][c-local]
    int b = blockIdx.z, n0 = blockIdx.x*64, c0 = blockIdx.y*32;
    int tx = threadIdx.x, ty = threadIdx.y;
    #pragma unroll
    for (int i = 0; i < 4; i++) {
        int c = c0 + ty + i*8;
        int n = n0 + tx*2;
        float2 v = *(const float2*)&x[(b*C_ + c)*N_ + n];
        __nv_bfloat16 h0, l0, h1, l1;
        split_bf16(v.x, h0, l0); split_bf16(v.y, h1, l1);
        uint hw = (uint)__bfloat16_as_ushort(h0) | ((uint)__bfloat16_as_ushort(h1) << 16);
        uint lw = (uint)__bfloat16_as_ushort(l0) | ((uint)__bfloat16_as_ushort(l1) << 16);
        *(uint*)&g_xh[(b*C_ + c)*N_ + n] = hw;
        *(uint*)&g_xl[(b*C_ + c)*N_ + n] = lw;
        t[tx*2][ty + i*8]     = v.x;
        t[tx*2 + 1][ty + i*8] = v.y;
    }
    __syncthreads();
    #pragma unroll
    for (int i = 0; i < 8; i++) {
        int nn = ty + i*8;
        g_xT[(b*N_ + n0 + nn)*C_ + c0 + tx] = t[nn][tx];
    }
}

// ----------------------------- k_prep -----------------------------
__global__ void __launch_bounds__(256) k_prep(
    const float* __restrict__ sem_w, const float* __restrict__ sem_b,
    const float* __restrict__ q_w,  const float* __restrict__ k_w,
    const float* __restrict__ v_w,  const float* __restrict__ fuse_w) {
    int blk = blockIdx.x, tid = threadIdx.x;
    if (blk < 10) {
        #pragma unroll
        for (int it = 0; it < 16; it++) {
            int e = tid + it*256;
            int r = blk*16 + (e >> 8), c = e & 255;
            float val = (r < 32) ? sem_w[r*C_ + c]
                      : (r < 96) ? q_w[(r-32)*C_ + c]
                                 : k_w[(r-96)*C_ + c];
            __nv_bfloat16 h, l; split_bf16(val, h, l);
            g_Wh[r*C_ + c] = h; g_Wl[r*C_ + c] = l;
            if (c == 0) g_bias[r] = (r < 32) ? sem_b[r] : 0.f;
        }
    } else {
        int r0 = 160 + (blk-10)*8;
        __shared__ float fw[8*256];
        #pragma unroll
        for (int it = 0; it < 8; it++) {
            int e = tid + it*256;
            fw[e] = fuse_w[(r0-160)*C_ + e];
        }
        __syncthreads();
        float acc[8] = {};
        for (int m = 0; m < C_; m++) {
            float v = v_w[m*C_ + tid];
            #pragma unroll
            for (int rr = 0; rr < 8; rr++) acc[rr] += fw[rr*256 + m] * v;
        }
        #pragma unroll
        for (int rr = 0; rr < 8; rr++) {
            int r = r0 + rr;
            __nv_bfloat16 h, l; split_bf16(acc[rr], h, l);
            g_Wh[r*C_ + tid] = h; g_Wl[r*C_ + tid] = l;
            if (tid == 0) g_bias[r] = 0.f;
        }
    }
}

// ----------------------------- k_gemm (cp.async + ldmatrix bf16-split) -----------------------------
__device__ __forceinline__ void mma16816(float* d, const uint* a, uint b0, uint b1) {
    asm volatile(
        "mma.sync.aligned.m16n8k16.row.col.f32.bf16.bf16.f32 "
        "{%0,%1,%2,%3}, {%4,%5,%6,%7}, {%8,%9}, {%0,%1,%2,%3};"
        : "+f"(d[0]), "+f"(d[1]), "+f"(d[2]), "+f"(d[3])
        : "r"(a[0]), "r"(a[1]), "r"(a[2]), "r"(a[3]), "r"(b0), "r"(b1));
}
__device__ __forceinline__ void ldsm4(uint* r, uint addr) {
    asm volatile("ldmatrix.sync.aligned.m8n8.x4.shared.b16 {%0,%1,%2,%3}, [%4];"
        : "=r"(r[0]), "=r"(r[1]), "=r"(r[2]), "=r"(r[3]) : "r"(addr));
}
__device__ __forceinline__ void ldsm4t(uint* r, uint addr) {
    asm volatile("ldmatrix.sync.aligned.m8n8.x4.trans.shared.b16 {%0,%1,%2,%3}, [%4];"
        : "=r"(r[0]), "=r"(r[1]), "=r"(r[2]), "=r"(r[3]) : "r"(addr));
}
__device__ __forceinline__ void cpa16(uint dst, const void* src) {
    asm volatile("cp.async.cg.shared.global [%0], [%1], 16;" :: "r"(dst), "l"(src));
}

// SMEM: A [buf][hl][128][40] bf16 (40960 B) + B [buf][hl][32][136] bf16 (34816 B) = 75776 B
#define GEMM_SMEM (4*128*40*2 + 4*32*136*2)

__device__ __forceinline__ void gemm_load(int buf, int kc, int r0, int n0,
                                          const __nv_bfloat16* xh, const __nv_bfloat16* xl,
                                          uint sa_base, uint sb_base, int tid) {
    #pragma unroll
    for (int i = 0; i < 4; i++) {
        int ch = tid + i*256;
        int hl = ch >> 9, rem = ch & 511;
        int r = rem >> 2, c = (rem & 3)*8;
        const __nv_bfloat16* src = (hl ? g_Wl : g_Wh) + (r0 + r)*C_ + kc + c;
        cpa16(sa_base + (((buf*2 + hl)*128 + r)*40 + c)*2, src);
    }
    #pragma unroll
    for (int i = 0; i < 4; i++) {
        int ch = tid + i*256;
        int hl = ch >> 9, rem = ch & 511;
        int k = rem >> 4, c = (rem & 15)*8;
        const __nv_bfloat16* src = (hl ? xl : xh) + (kc + k)*N_ + n0 + c;
        cpa16(sb_base + (((buf*2 + hl)*32 + k)*136 + c)*2, src);
    }
    asm volatile("cp.async.commit_group;" ::: "memory");
}

__global__ void __launch_bounds__(256) k_gemm() {
    extern __shared__ __align__(16) char dsm[];
    uint sa_base = cvta_smem(dsm);
    uint sb_base = sa_base + 4*128*40*2;

    int n0 = blockIdx.x*128, r0 = blockIdx.y*128, b = blockIdx.z;
    int tid = threadIdx.x, lane = tid & 31, wid = tid >> 5;
    int wm = wid & 3, wn = wid >> 2;
    const __nv_bfloat16* xh = g_xh + b*C_*N_;
    const __nv_bfloat16* xl = g_xl + b*C_*N_;

    float acc[2][8][4];
    #pragma unroll
    for (int mt = 0; mt < 2; mt++)
        #pragma unroll
        for (int nt = 0; nt < 8; nt++)
            #pragma unroll
            for (int i = 0; i < 4; i++) acc[mt][nt][i] = 0.f;

    gemm_load(0, 0, r0, n0, xh, xl, sa_base, sb_base, tid);
    int buf = 0;
    for (int kt = 0; kt < 8; kt++) {
        if (kt < 7) {
            gemm_load(buf^1, (kt+1)*32, r0, n0, xh, xl, sa_base, sb_base, tid);
            asm volatile("cp.async.wait_group 1;" ::: "memory");
        } else {
            asm volatile("cp.async.wait_group 0;" ::: "memory");
        }
        __syncthreads();
        #pragma unroll
        for (int seg = 0; seg < 3; seg++) {
            int ah = (seg == 2) ? 1 : 0;       // Wl only in seg 2
            int bh = (seg == 1) ? 1 : 0;       // xl only in seg 1
            #pragma unroll
            for (int k16 = 0; k16 < 2; k16++) {
                uint a0[4], a1[4];
                int ra = wm*32 + (lane & 15);
                int kcol = k16*16 + (lane >> 4)*8;
                ldsm4(a0, sa_base + (((buf*2+ah)*128 + ra)*40 + kcol)*2);
                ldsm4(a1, sa_base + (((buf*2+ah)*128 + ra + 16)*40 + kcol)*2);
                int krow = k16*16 + (lane & 15);
                #pragma unroll
                for (int np = 0; np < 4; np++) {
                    int nc = wn*64 + np*16 + (lane >> 4)*8;
                    uint bb[4];
                    ldsm4t(bb, sb_base + (((buf*2+bh)*32 + krow)*136 + nc)*2);
                    mma16816(acc[0][np*2],   a0, bb[0], bb[1]);
                    mma16816(acc[1][np*2],   a1, bb[0], bb[1]);
                    mma16816(acc[0][np*2+1], a0, bb[2], bb[3]);
                    mma16816(acc[1][np*2+1], a1, bb[2], bb[3]);
                }
            }
        }
        __syncthreads();
        buf ^= 1;
    }

    #pragma unroll
    for (int mt = 0; mt < 2; mt++) {
        int r = r0 + wm*32 + mt*16 + (lane >> 2);
        #pragma unroll
        for (int nt = 0; nt < 8; nt++) {
            int n = n0 + wn*64 + nt*8 + (lane & 3)*2;
            if (r < R_) {
                float bi = g_bias[r];
                *(float2*)&g_P[(b*R_ + r)*N_ + n] =
                    make_float2(acc[mt][nt][0] + bi, acc[mt][nt][1] + bi);
            }
            if (r + 8 < R_) {
                float bi2 = g_bias[r + 8];
                *(float2*)&g_P[(b*R_ + r + 8)*N_ + n] =
                    make_float2(acc[mt][nt][2] + bi2, acc[mt][nt][3] + bi2);
            }
        }
    }
}

// ----------------------------- k_sem -----------------------------
__global__ void __launch_bounds__(256) k_sem() {
    int g = blockIdx.x*256 + threadIdx.x;      // 32768 = 8192 pos * 4
    int pos = g >> 2, s = g & 3;
    int b = pos >> 12, n = pos & (N_-1);
    float l[8];
    float mx = -INFINITY; int am = K_;
    #pragma unroll
    for (int j = 0; j < 8; j++) {
        l[j] = g_P[(b*R_ + s*8 + j)*N_ + n];
        if (l[j] > mx) { mx = l[j]; am = s*8 + j; }
    }
    #pragma unroll
    for (int off = 1; off <= 2; off <<= 1) {
        float ov = __shfl_xor_sync(0xFFFFFFFFu, mx, off);
        int   oa = __shfl_xor_sync(0xFFFFFFFFu, am, off);
        if (ov > mx || (ov == mx && oa < am)) { mx = ov; am = oa; }
    }
    float sum = 0.f;
    #pragma unroll
    for (int j = 0; j < 8; j++) { l[j] = expf(l[j] - mx); sum += l[j]; }
    #pragma unroll
    for (int off = 1; off <= 2; off <<= 1)
        sum += __shfl_xor_sync(0xFFFFFFFFu, sum, off);
    float inv = 1.f/sum;
    #pragma unroll
    for (int j = 0; j < 8; j++) g_sem[(b*K_ + s*8 + j)*N_ + n] = l[j]*inv;
    if (s == 0) {
        int slot = atomicAdd(&g_cnt[b*K_ + am], 1);
        g_plist[(b*K_+am)*N_ + slot] = n;
    }
}

// ----------------------------- k_sel -----------------------------
__global__ void __launch_bounds__(512) k_sel() {
    __shared__ ull cand[4096];                     // first 16 KB aliased as hist
    __shared__ ull win[256];
    __shared__ int sufc[256];
    __shared__ int s_tc, s_cA, s_t, s_A, s_nw, s_nc;
    unsigned* hist = (unsigned*)cand;

    int bk = blockIdx.x; int b = bk >> 5, k = bk & 31;
    int tid = threadIdx.x;
    const float* row = g_sem + (b*K_ + k)*N_;

    for (int i = tid; i < 4096; i += 512) hist[i] = 0;
    __syncthreads();

    unsigned vb[8];
    #pragma unroll
    for (int j = 0; j < 8; j++) {
        vb[j] = __float_as_uint(row[tid + j*512]);
        atomicAdd(&hist[vb[j] >> 20], 1);
    }
    __syncthreads();

    if (tid < 256) {
        int cs = 0;
        #pragma unroll
        for (int h = 0; h < 16; h++) cs += hist[tid*16 + h];
        sufc[tid] = cs;
    }
    __syncthreads();
    #pragma unroll
    for (int st = 1; st < 256; st <<= 1) {
        int add = (tid < 256 && tid + st < 256) ? sufc[tid + st] : 0;
        __syncthreads();
        if (tid < 256) sufc[tid] += add;
        __syncthreads();
    }
    if (tid < 256) {
        int nxt = (tid < 255) ? sufc[tid + 1] : 0;
        if (sufc[tid] >= M_ && nxt < M_) { s_tc = tid; s_cA = nxt; }
    }
    if (tid == 0) { s_nw = 0; s_nc = 0; }
    __syncthreads();
    int tc = s_tc, cA = s_cA;
    if (tid < 16) {
        int sg = 0;
        for (int j = tid; j < 16; j++) sg += hist[tc*16 + j];
        int hi = hist[tc*16 + tid];
        if (cA + sg >= M_ && cA + sg - hi < M_) { s_t = tc*16 + tid; s_A = cA + sg - hi; }
    }
    __syncthreads();
    int t = s_t, A = s_A, s = M_ - A;
    __syncthreads();   // hist reads done; cand may be overwritten

    #pragma unroll
    for (int j = 0; j < 8; j++) {
        unsigned v = vb[j];
        int idx = tid + j*512;
        unsigned bkt = v >> 20;
        ull key = ((ull)v << 32) | (unsigned)(0xFFFFFFFFu - (unsigned)idx);
        if ((int)bkt > t) { int p = atomicAdd(&s_nw, 1); win[p] = ~key; }
        else if ((int)bkt == t) { int p = atomicAdd(&s_nc, 1); cand[p] = ~key; }
    }
    __syncthreads();

    int nc = s_nc;
    int P = 1; while (P < nc) P <<= 1;
    for (int i = tid; i < P; i += 512) if (i >= nc) cand[i] = 0xFFFFFFFFFFFFFFFFULL;
    __syncthreads();
    for (int sz = 2; sz <= P; sz <<= 1) {
        for (int str = sz >> 1; str > 0; str >>= 1) {
            for (int i = tid; i < P; i += 512) {
                int l = i ^ str;
                if (l > i) {
                    ull a = cand[i], c2 = cand[l];
                    bool up = ((i & sz) == 0);
                    if ((a > c2) == up) { cand[i] = c2; cand[l] = a; }
                }
            }
            __syncthreads();
        }
    }
    for (int i = tid; i < s; i += 512) win[A + i] = cand[i];
    __syncthreads();
    for (int sz = 2; sz <= 256; sz <<= 1) {
        for (int str = sz >> 1; str > 0; str >>= 1) {
            if (tid < 256) {
                int i = tid, l = i ^ str;
                if (l > i) {
                    ull a = win[i], c2 = win[l];
                    bool up = ((i & sz) == 0);
                    if ((a > c2) == up) { win[i] = c2; win[l] = a; }
                }
            }
            __syncthreads();
        }
    }
    if (tid < 256) g_ti[(b*K_ + k)*M_ + tid] = (int)(unsigned)(win[tid] & 0xFFFFFFFFu);
}

// ----------------------------- k_transpA (q, k, fv) -----------------------------
__global__ void k_transpA() {
    __shared__ float t[32][33];
    int b = blockIdx.z, x0 = blockIdx.x*32, y = blockIdx.y;
    const float* src; float* dst; int r0, Rr;
    if      (y < 2)  { src = g_P + (b*R_ + 32)*N_;  dst = g_qT  + b*N_*D_; r0 = y*32;     Rr = D_; }
    else if (y < 4)  { src = g_P + (b*R_ + 96)*N_;  dst = g_kT  + b*N_*D_; r0 = (y-2)*32; Rr = D_; }
    else             { src = g_P + (b*R_ + 160)*N_; dst = g_fvT + b*N_*C_; r0 = (y-4)*32; Rr = C_; }
    int tx = threadIdx.x, ty = threadIdx.y;
    #pragma unroll
    for (int i = 0; i < 32; i += 8)
        t[ty+i][tx] = src[(r0 + ty + i)*N_ + x0 + tx];
    __syncthreads();
    #pragma unroll
    for (int i = 0; i < 32; i += 8)
        dst[(x0 + ty + i)*Rr + r0 + tx] = t[tx][ty+i];
}

__global__ void k_transpO(float* __restrict__ out) {
    __shared__ float t[32][33];
    int b = blockIdx.z, c0 = blockIdx.x*32, n0 = blockIdx.y*32;
    int tx = threadIdx.x, ty = threadIdx.y;
    #pragma unroll
    for (int i = 0; i < 32; i += 8)
        t[ty+i][tx] = g_outT[b*N_*C_ + (n0 + ty + i)*C_ + c0 + tx];
    __syncthreads();
    #pragma unroll
    for (int i = 0; i < 32; i += 8)
        out[b*C_*N_ + (c0 + ty + i)*N_ + n0 + tx] = t[tx][ty+i];
}

// ----------------------------- k_region (atomic accumulate) -----------------------------
__global__ void __launch_bounds__(256) k_region() {
    __shared__ float ss[32*68];
    __shared__ float ps[64*68];
    int ct = blockIdx.x, sp = blockIdx.y, b = blockIdx.z;
    int tid = threadIdx.x;
    int kk = tid & 31, cg = tid >> 5;
    float acc[8] = {};
    for (int nch = 0; nch < 4; nch++) {
        int nn0 = sp*256 + nch*64;
        #pragma unroll
        for (int i = 0; i < 8; i++) {
            int e = tid + i*256; int kr = e >> 6, nn = e & 63;
            ss[kr*68+nn] = g_sem[(b*K_+kr)*N_ + nn0 + nn];
        }
        #pragma unroll
        for (int i = 0; i < 16; i++) {
            int e = tid + i*256; int c = e >> 6, nn = e & 63;
            ps[c*68+nn] = g_P[(b*R_ + 96 + ct*64 + c)*N_ + nn0 + nn];
        }
        __syncthreads();
        #pragma unroll 4
        for (int nn = 0; nn < 64; nn += 4) {
            float4 sv = *(const float4*)&ss[kk*68 + nn];
            #pragma unroll
            for (int j = 0; j < 8; j++) {
                float4 pv = *(const float4*)&ps[(cg*8+j)*68 + nn];
                acc[j] += sv.x*pv.x;
                acc[j] += sv.y*pv.y;
                acc[j] += sv.z*pv.z;
                acc[j] += sv.w*pv.w;
            }
        }
        __syncthreads();
    }
    #pragma unroll
    for (int j = 0; j < 8; j++) {
        int o = ct*64 + cg*8 + j;
        if (o < 64) atomicAdd(&g_RK[(b*K_+kk)*D_ + o], acc[j]);
        else        atomicAdd(&g_RFV[(b*K_+kk)*C_ + (o-64)], acc[j]);
    }
}

// ----------------------------- k_main -----------------------------
__global__ void __launch_bounds__(256) k_main(const float* __restrict__ alpha_p,
                                              const float* __restrict__ fuse_b,
                                              const float* __restrict__ ln_g,
                                              const float* __restrict__ ln_b) {
    extern __shared__ float sm[];
    float* s_pkT = sm;                         // 64*257
    float* s_rfv = s_pkT + 64*257;             // 32*256
    float* s_rk  = s_rfv + 32*256;             // 32*65
    int*   s_pool= (int*)(s_rk + 32*65);       // 256

    int reg = blockIdx.y, b = blockIdx.z;
    int cnt = g_cnt[b*K_ + reg];
    if ((int)blockIdx.x * 64 >= cnt) return;
    int tid = threadIdx.x, lane = tid & 31, w = tid >> 5;

    if (tid < M_) s_pool[tid] = g_ti[(b*K_+reg)*M_ + tid];
    __syncthreads();
    #pragma unroll 4
    for (int i = 0; i < 64; i++) {
        int e = tid + i*256;
        int m = e >> 6, d = e & 63;
        s_pkT[d*257 + m] = g_kT[(b*N_ + s_pool[m])*D_ + d];
    }
    #pragma unroll
    for (int i = 0; i < 32; i++) s_rfv[tid + i*256] = g_RFV[b*K_*C_ + tid + i*256];
    #pragma unroll
    for (int i = 0; i < 8; i++) {
        int e = tid + i*256; int kk = e >> 6, d = e & 63;
        s_rk[kk*65+d] = g_RK[(b*K_+kk)*D_ + d];
    }
    __syncthreads();

    float a = 1.f/(1.f + expf(-alpha_p[0]));

    for (int chunk = blockIdx.x; chunk*64 < cnt; chunk += 4) {
        int base = chunk*64;
        int pend = min(base+64, cnt);
        for (int g = 0; g < 2; g++) {
            int p0 = base + w*8 + g*4;
            if (p0 >= pend) break;
            int nv = min(4, pend - p0);
            int n[4]; float q0[4], q1[4];
            #pragma unroll
            for (int i = 0; i < 4; i++) {
                if (i < nv) {
                    n[i] = g_plist[(b*K_+reg)*N_ + p0 + i];
                    q0[i] = g_qT[(b*N_+n[i])*D_ + lane];
                    q1[i] = g_qT[(b*N_+n[i])*D_ + 32 + lane];
                } else { n[i] = 0; q0[i] = 0.f; q1[i] = 0.f; }
            }

            float sims[4][8] = {};
            #pragma unroll
            for (int dh = 0; dh < 2; dh++) {
                #pragma unroll 2
                for (int dd = 0; dd < 32; dd++) {
                    const float* rowp = s_pkT + (dh*32+dd)*257;
                    float r8[8];
                    #pragma unroll
                    for (int mi = 0; mi < 8; mi++) r8[mi] = rowp[mi*32 + lane];
                    #pragma unroll
                    for (int i = 0; i < 4; i++) {
                        float qd = __shfl_sync(0xFFFFFFFFu, dh ? q1[i] : q0[i], dd);
                        #pragma unroll
                        for (int mi = 0; mi < 8; mi++) sims[i][mi] += qd * r8[mi];
                    }
                }
            }

            #pragma unroll 1
            for (int i = 0; i < 4; i++) {
                if (i >= nv) break;
                float sv[8];
                #pragma unroll
                for (int mi = 0; mi < 8; mi++) sv[mi] = sims[i][mi] * INVSCALE;

                float tv[8]; int tm[8];
                unsigned used = 0;
                #pragma unroll
                for (int t = 0; t < 8; t++) {
                    float bv = -INFINITY; int bm = 1 << 30;
                    #pragma unroll
                    for (int mi = 0; mi < 8; mi++) {
                        if (!(used & (1u << mi))) {
                            float v = sv[mi]; int m = mi*32 + lane;
                            if (v > bv || (v == bv && m < bm)) { bv = v; bm = m; }
                        }
                    }
                    #pragma unroll
                    for (int off = 16; off > 0; off >>= 1) {
                        float ov = __shfl_xor_sync(0xFFFFFFFFu, bv, off);
                        int   om = __shfl_xor_sync(0xFFFFFFFFu, bm, off);
                        if (ov > bv || (ov == bv && om < bm)) { bv = ov; bm = om; }
                    }
                    tv[t] = bv; tm[t] = bm;
                    if ((bm & 31) == lane) used |= 1u << (bm >> 5);
                }
                float ww[8], wsum = 0.f;
                #pragma unroll
                for (int t = 0; t < 8; t++) { ww[t] = expf(tv[t] - tv[0]); wsum += ww[t]; }
                float winv = 1.f/wsum;
                float fs[8] = {};
                #pragma unroll
                for (int t = 0; t < 8; t++) {
                    float att = ww[t]*winv;
                    int gidx = s_pool[tm[t]];
                    const float* fvrow = g_fvT + (b*N_ + gidx)*C_;
                    #pragma unroll
                    for (int j = 0; j < 8; j++) fs[j] += att * fvrow[j*32 + lane];
                }
                float lg = 0.f;
                #pragma unroll
                for (int dh = 0; dh < 2; dh++) {
                    #pragma unroll 4
                    for (int dd = 0; dd < 32; dd++) {
                        float qd = __shfl_sync(0xFFFFFFFFu, dh ? q1[i] : q0[i], dd);
                        lg += qd * s_rk[lane*65 + dh*32 + dd];
                    }
                }
                lg *= INVSCALE;
                float mx = lg;
                #pragma unroll
                for (int off = 16; off > 0; off >>= 1)
                    mx = fmaxf(mx, __shfl_xor_sync(0xFFFFFFFFu, mx, off));
                float ev = expf(lg - mx), es = ev;
                #pragma unroll
                for (int off = 16; off > 0; off >>= 1) es += __shfl_xor_sync(0xFFFFFFFFu, es, off);
                float attn = ev/es;
                float fc[8] = {};
                #pragma unroll 4
                for (int kk = 0; kk < K_; kk++) {
                    float ak = __shfl_sync(0xFFFFFFFFu, attn, kk);
                    const float* rrow = s_rfv + kk*256;
                    #pragma unroll
                    for (int j = 0; j < 8; j++) fc[j] += ak * rrow[j*32 + lane];
                }
                float pre[8], sum = 0.f, sq = 0.f;
                const float* xrow = g_xT + (b*N_+n[i])*C_;
                #pragma unroll
                for (int j = 0; j < 8; j++) {
                    int c = j*32 + lane;
                    float f = a*fc[j] + (1.f - a)*fs[j] + fuse_b[c];
                    float v = xrow[c] + f;
                    pre[j] = v; sum += v; sq += v*v;
                }
                #pragma unroll
                for (int off = 16; off > 0; off >>= 1) {
                    sum += __shfl_xor_sync(0xFFFFFFFFu, sum, off);
                    sq  += __shfl_xor_sync(0xFFFFFFFFu, sq,  off);
                }
                float mu = sum * (1.f/256.f);
                float var = sq * (1.f/256.f) - mu*mu;
                float rstd = rsqrtf(var + 1e-5f);
                float* orow = g_outT + (b*N_+n[i])*C_;
                #pragma unroll
                for (int j = 0; j < 8; j++) {
                    int c = j*32 + lane;
                    orow[c] = (pre[j]-mu)*rstd*ln_g[c] + ln_b[c];
                }
            }
        }
    }
}

// ----------------------------- launch -----------------------------
extern "C" void kernel_launch(void* const* d_in, const int* in_sizes, int n_in,
                              void* d_out, int out_size) {
    const float* x      = (const float*)d_in[0];
    const float* sem_w  = (const float*)d_in[1];
    const float* sem_b  = (const float*)d_in[2];
    const float* q_w    = (const float*)d_in[3];
    const float* k_w    = (const float*)d_in[4];
    const float* v_w    = (const float*)d_in[5];
    const float* fuse_w = (const float*)d_in[6];
    const float* fuse_b = (const float*)d_in[7];
    const float* alpha  = (const float*)d_in[8];
    const float* ln_g   = (const float*)d_in[9];
    const float* ln_b   = (const float*)d_in[10];
    float* out = (float*)d_out;

    const int SMEM_MAIN = (64*257 + 32*256 + 32*65)*4 + 256*4;
    cudaFuncSetAttribute((const void*)k_main,
                         cudaFuncAttributeMaxDynamicSharedMemorySize, SMEM_MAIN);
    cudaFuncSetAttribute((const void*)k_gemm,
                         cudaFuncAttributeMaxDynamicSharedMemorySize, GEMM_SMEM);

    k_zero<<<48, 256>>>();                                     // #1
    k_cvtx<<<dim3(64, 8, B_), dim3(32, 8)>>>(x);               // #2
    k_prep<<<42, 256>>>(sem_w, sem_b, q_w, k_w, v_w, fuse_w);  // #3
    k_gemm<<<dim3(32, 4, B_), 256, GEMM_SMEM>>>();             // #4  <- ncu slot
    k_sem<<<128, 256>>>();                                     // #5
    k_sel<<<B_*K_, 512>>>();                                   // #6
    k_transpA<<<dim3(128, 12, B_), dim3(32, 8)>>>();           // #7
    k_region<<<dim3(5, 16, B_), 256>>>();                      // #8
    k_main<<<dim3(4, K_, B_), 256, SMEM_MAIN>>>(alpha, fuse_b, ln_g, ln_b); // #9
    k_transpO<<<dim3(8, 128, B_), dim3(32, 8)>>>(out);         // #10
}